// round 6
// baseline (speedup 1.0000x reference)
#include <cuda_runtime.h>
#include <cstdint>

// Problem constants (fixed shapes per reference)
#define N_NODES   8192
#define IN_F      1024
#define OUT_F     512
#define N_EDGES   262144
#define MASK_ROW_WORDS (N_NODES / 32)
#define MASK_WORDS     (N_NODES * MASK_ROW_WORDS)     // 8 MB
#define NBR_STRIDE 192

// Device-global scratch (allocation-free rule)
__device__ uint32_t g_mask[MASK_WORDS];
__device__ float    g_hidden[N_NODES * OUT_F];        // 16 MB
__device__ uint16_t g_nbr[N_NODES * NBR_STRIDE];
__device__ int      g_cnt[N_NODES];
__device__ int      g_is64;
// bf16 hi/lo splits, packed bf16x2 per u32 along K (k-contiguous)
__device__ uint32_t g_xhi[N_NODES * (IN_F / 2)];      // 16 MB
__device__ uint32_t g_xlo[N_NODES * (IN_F / 2)];      // 16 MB
__device__ uint32_t g_whi[OUT_F * (IN_F / 2)];        // 1 MB
__device__ uint32_t g_wlo[OUT_F * (IN_F / 2)];        // 1 MB

// ---------------------------------------------------------------------------
// Graph preprocessing (unchanged)
// ---------------------------------------------------------------------------
__global__ void detect_dtype_kernel(const int* __restrict__ ei32) {
    int lane = threadIdx.x;
    int nonzero = 0;
    #pragma unroll
    for (int i = 0; i < 3; i++) {
        if (ei32[2 * (lane + 32 * i) + 1] != 0) nonzero = 1;
    }
    unsigned any = __ballot_sync(0xFFFFFFFFu, nonzero);
    if (lane == 0) g_is64 = (any == 0u) ? 1 : 0;
}

__global__ void zero_mask_kernel() {
    int idx = blockIdx.x * blockDim.x + threadIdx.x;
    uint4* p = reinterpret_cast<uint4*>(g_mask);
    int n4 = MASK_WORDS / 4;
    for (int i = idx; i < n4; i += gridDim.x * blockDim.x)
        p[i] = make_uint4(0u, 0u, 0u, 0u);
    if (idx < N_NODES) g_cnt[idx] = 0;
}

__global__ void build_mask_kernel(const int* __restrict__ ei32) {
    int e = blockIdx.x * blockDim.x + threadIdx.x;
    if (e >= N_EDGES) return;
    int src, dst;
    if (g_is64) {
        src = ei32[2 * e];
        dst = ei32[2 * (N_EDGES + e)];
    } else {
        src = ei32[e];
        dst = ei32[N_EDGES + e];
    }
    if ((unsigned)src >= N_NODES || (unsigned)dst >= N_NODES) return;
    uint32_t bit = 1u << (dst & 31);
    uint32_t old = atomicOr(&g_mask[src * MASK_ROW_WORDS + (dst >> 5)], bit);
    if (!(old & bit)) {
        int pos = atomicAdd(&g_cnt[src], 1);
        if (pos < NBR_STRIDE)
            g_nbr[src * NBR_STRIDE + pos] = (uint16_t)dst;
    }
}

// ---------------------------------------------------------------------------
// fp32 -> bf16 hi/lo split (packed bf16x2: low 16 bits = even k)
// ---------------------------------------------------------------------------
__device__ __forceinline__ void split_pair(float2 v, uint32_t& hi, uint32_t& lo) {
    asm("cvt.rn.satfinite.bf16x2.f32 %0, %1, %2;" : "=r"(hi) : "f"(v.y), "f"(v.x));
    float h0 = __uint_as_float(hi << 16);
    float h1 = __uint_as_float(hi & 0xFFFF0000u);
    float r0 = v.x - h0;
    float r1 = v.y - h1;
    asm("cvt.rn.satfinite.bf16x2.f32 %0, %1, %2;" : "=r"(lo) : "f"(r1), "f"(r0));
}

__global__ void convert_x_kernel(const float* __restrict__ x) {
    int n = N_NODES * (IN_F / 2);
    const float2* x2 = reinterpret_cast<const float2*>(x);
    for (int i = blockIdx.x * blockDim.x + threadIdx.x; i < n; i += gridDim.x * blockDim.x) {
        uint32_t hi, lo;
        split_pair(x2[i], hi, lo);
        g_xhi[i] = hi;
        g_xlo[i] = lo;
    }
}

__global__ void convert_w_kernel(const float* __restrict__ W) {
    int n = OUT_F * (IN_F / 2);
    const float2* w2 = reinterpret_cast<const float2*>(W);
    for (int i = blockIdx.x * blockDim.x + threadIdx.x; i < n; i += gridDim.x * blockDim.x) {
        uint32_t hi, lo;
        split_pair(w2[i], hi, lo);
        g_whi[i] = hi;
        g_wlo[i] = lo;
    }
}

// ---------------------------------------------------------------------------
// mma.sync bf16 split GEMM:  hidden = x @ W^T + b
// CTA tile 128x128, BK=32 (bf16), 512 threads = 16 warps (2m x 8n),
// warp tile 64x16 (identical inner structure to the proven R5 kernel).
// Double-buffered cp.async; 80B-padded smem rows (conflict-free ldmatrix).
// grid (4,64): A L2 traffic halved vs BN=64.
// ---------------------------------------------------------------------------
#define BM 128
#define BN 128
#define GEMM_THREADS 512
#define PAD_STRIDE 80          // bytes per 32-bf16 row (5 x 16B -> all banks)
#define ST_AH 0                // A-hi: 128 * 80 = 10240
#define ST_AL 10240            // A-lo
#define ST_BH 20480            // B-hi: 128 * 80 = 10240
#define ST_BL 30720            // B-lo
#define STAGE_SZ 40960
#define GEMM_SMEM (2 * STAGE_SZ)   // 81920 dynamic

__device__ __forceinline__ void cp16(uint32_t s, const void* g) {
    asm volatile("cp.async.cg.shared.global [%0], [%1], 16;" :: "r"(s), "l"(g) : "memory");
}

#define LDM_X4(r, addr) \
    asm volatile("ldmatrix.sync.aligned.m8n8.x4.shared.b16 {%0,%1,%2,%3}, [%4];" \
        : "=r"((r)[0]), "=r"((r)[1]), "=r"((r)[2]), "=r"((r)[3]) : "r"(addr))

#define MMA16816(c, a, b0, b1) \
    asm volatile("mma.sync.aligned.m16n8k16.row.col.f32.bf16.bf16.f32 " \
        "{%0,%1,%2,%3}, {%4,%5,%6,%7}, {%8,%9}, {%0,%1,%2,%3};" \
        : "+f"((c)[0]), "+f"((c)[1]), "+f"((c)[2]), "+f"((c)[3]) \
        : "r"((a)[0]), "r"((a)[1]), "r"((a)[2]), "r"((a)[3]), "r"(b0), "r"(b1))

__global__ __launch_bounds__(GEMM_THREADS, 1) void gemm_tc_kernel(const float* __restrict__ bias)
{
    extern __shared__ char smem[];
    const uint32_t sbase = (uint32_t)__cvta_generic_to_shared(smem);
    const int tid  = threadIdx.x;
    const int wid  = tid >> 5;
    const int lane = tid & 31;
    const int bm = blockIdx.y * BM;
    const int bn = blockIdx.x * BN;

    const int warp_m = wid >> 3;            // 0..1, 64 rows each
    const int warp_n = wid & 7;             // 0..7, 16 cols each

    float acc[4][2][4];
    #pragma unroll
    for (int i = 0; i < 4; i++)
        #pragma unroll
        for (int j = 0; j < 2; j++)
            #pragma unroll
            for (int k = 0; k < 4; k++) acc[i][j][k] = 0.f;

    // cp.async fill of one stage for K-chunk c (2048 x 16B, 4 per thread)
    auto issue = [&](int stage, int c) {
        uint32_t st = sbase + stage * STAGE_SZ;
        #pragma unroll
        for (int t = 0; t < 4; t++) {
            int i = tid + t * GEMM_THREADS;
            if (i < 1024) {                              // A tiles (128 rows)
                int half = i >> 9;                       // 0=hi 1=lo
                int idx = i & 511;
                int row = idx >> 2, seg = idx & 3;
                const uint32_t* gsrc = (half ? g_xlo : g_xhi)
                    + (size_t)(bm + row) * (IN_F / 2) + c * 16 + seg * 4;
                cp16(st + (half ? ST_AL : ST_AH) + row * PAD_STRIDE + seg * 16, gsrc);
            } else {                                     // B tiles (128 rows)
                int j = i - 1024;
                int half = j >> 9;
                int idx = j & 511;
                int row = idx >> 2, seg = idx & 3;
                const uint32_t* gsrc = (half ? g_wlo : g_whi)
                    + (size_t)(bn + row) * (IN_F / 2) + c * 16 + seg * 4;
                cp16(st + (half ? ST_BL : ST_BH) + row * PAD_STRIDE + seg * 16, gsrc);
            }
        }
        asm volatile("cp.async.commit_group;" ::: "memory");
    };

    // ldmatrix per-thread source rows (same as proven kernel)
    const int a_row  = warp_m * 64 + (lane & 15);     // + im*16
    const int a_half = lane >> 4;                     // k byte-half
    const int b_row  = warp_n * 16 + ((lane & 16) >> 1) + (lane & 7);
    const int b_half = (lane >> 3) & 1;

    issue(0, 0);

    const int NCHUNK = IN_F / 32;   // 32
    for (int c = 0; c < NCHUNK; c++) {
        if (c + 1 < NCHUNK) {
            issue((c + 1) & 1, c + 1);
            asm volatile("cp.async.wait_group 1;" ::: "memory");
        } else {
            asm volatile("cp.async.wait_group 0;" ::: "memory");
        }
        __syncthreads();

        const uint32_t st = sbase + (c & 1) * STAGE_SZ;
        #pragma unroll
        for (int ks = 0; ks < 2; ks++) {
            const int kb = ks * 32;                   // 16 bf16 = 32 bytes
            uint32_t ah[4][4], al[4][4];
            #pragma unroll
            for (int im = 0; im < 4; im++) {
                uint32_t addr = st + ST_AH + (a_row + im * 16) * PAD_STRIDE + kb + a_half * 16;
                LDM_X4(ah[im], addr);
                LDM_X4(al[im], addr + (ST_AL - ST_AH));
            }
            uint32_t bh[4], bl[4];
            {
                uint32_t addr = st + ST_BH + b_row * PAD_STRIDE + kb + b_half * 16;
                LDM_X4(bh, addr);
                LDM_X4(bl, addr + (ST_BL - ST_BH));
            }
            #pragma unroll
            for (int im = 0; im < 4; im++) {
                #pragma unroll
                for (int in = 0; in < 2; in++) {
                    MMA16816(acc[im][in], ah[im], bh[in * 2], bh[in * 2 + 1]); // hh
                    MMA16816(acc[im][in], ah[im], bl[in * 2], bl[in * 2 + 1]); // hl
                    MMA16816(acc[im][in], al[im], bh[in * 2], bh[in * 2 + 1]); // lh
                }
            }
        }
        __syncthreads();
    }

    // Epilogue: add bias, store fp32 hidden
    const int er = lane >> 2;
    const int ec = (lane & 3) * 2;
    #pragma unroll
    for (int im = 0; im < 4; im++) {
        int r0 = bm + warp_m * 64 + im * 16 + er;
        #pragma unroll
        for (int in = 0; in < 2; in++) {
            int col = bn + warp_n * 16 + in * 8 + ec;
            float b0 = __ldg(&bias[col]);
            float b1 = __ldg(&bias[col + 1]);
            float2 v0 = make_float2(acc[im][in][0] + b0, acc[im][in][1] + b1);
            float2 v1 = make_float2(acc[im][in][2] + b0, acc[im][in][3] + b1);
            *reinterpret_cast<float2*>(&g_hidden[(size_t)r0 * OUT_F + col]) = v0;
            *reinterpret_cast<float2*>(&g_hidden[(size_t)(r0 + 8) * OUT_F + col]) = v1;
        }
    }
}

// ---------------------------------------------------------------------------
// out[row] = relu( sum_{j in nbr[row]} hidden[j] )  (unchanged)
// ---------------------------------------------------------------------------
__global__ __launch_bounds__(128) void aggregate_kernel(float* __restrict__ out) {
    __shared__ uint16_t s_nbr[NBR_STRIDE];
    __shared__ int s_deg;

    const int row = blockIdx.x;
    const int col = threadIdx.x;

    if (col == 0) s_deg = min(g_cnt[row], NBR_STRIDE);
    __syncthreads();
    const int deg = s_deg;
    for (int i = col; i < deg; i += 128)
        s_nbr[i] = g_nbr[row * NBR_STRIDE + i];
    __syncthreads();

    const float4* H = reinterpret_cast<const float4*>(g_hidden);

    float4 a0 = make_float4(0.f, 0.f, 0.f, 0.f);
    float4 a1 = make_float4(0.f, 0.f, 0.f, 0.f);
    float4 a2 = make_float4(0.f, 0.f, 0.f, 0.f);
    float4 a3 = make_float4(0.f, 0.f, 0.f, 0.f);

    int i = 0;
    for (; i + 4 <= deg; i += 4) {
        int j0 = s_nbr[i + 0], j1 = s_nbr[i + 1];
        int j2 = s_nbr[i + 2], j3 = s_nbr[i + 3];
        float4 v0 = H[j0 * 128 + col];
        float4 v1 = H[j1 * 128 + col];
        float4 v2 = H[j2 * 128 + col];
        float4 v3 = H[j3 * 128 + col];
        a0.x += v0.x; a0.y += v0.y; a0.z += v0.z; a0.w += v0.w;
        a1.x += v1.x; a1.y += v1.y; a1.z += v1.z; a1.w += v1.w;
        a2.x += v2.x; a2.y += v2.y; a2.z += v2.z; a2.w += v2.w;
        a3.x += v3.x; a3.y += v3.y; a3.z += v3.z; a3.w += v3.w;
    }
    for (; i < deg; i++) {
        int j = s_nbr[i];
        float4 v = H[j * 128 + col];
        a0.x += v.x; a0.y += v.y; a0.z += v.z; a0.w += v.w;
    }

    float4 r;
    r.x = fmaxf(a0.x + a1.x + a2.x + a3.x, 0.f);
    r.y = fmaxf(a0.y + a1.y + a2.y + a3.y, 0.f);
    r.z = fmaxf(a0.z + a1.z + a2.z + a3.z, 0.f);
    r.w = fmaxf(a0.w + a1.w + a2.w + a3.w, 0.f);
    reinterpret_cast<float4*>(out)[row * 128 + col] = r;
}

// ---------------------------------------------------------------------------
// Launch
// ---------------------------------------------------------------------------
extern "C" void kernel_launch(void* const* d_in, const int* in_sizes, int n_in,
                              void* d_out, int out_size)
{
    const float* x    = (const float*)d_in[0];
    const float* W    = (const float*)d_in[1];
    const float* bias = (const float*)d_in[2];
    const int*   ei   = (const int*)d_in[3];
    float*       out  = (float*)d_out;

    (void)in_sizes; (void)n_in; (void)out_size;

    cudaFuncSetAttribute(gemm_tc_kernel,
                         cudaFuncAttributeMaxDynamicSharedMemorySize, GEMM_SMEM);

    detect_dtype_kernel<<<1, 32>>>(ei);
    zero_mask_kernel<<<1024, 256>>>();
    build_mask_kernel<<<N_EDGES / 256, 256>>>(ei);

    convert_x_kernel<<<2048, 256>>>(x);
    convert_w_kernel<<<512, 256>>>(W);

    dim3 ggrid(OUT_F / BN, N_NODES / BM);   // (4, 64)
    gemm_tc_kernel<<<ggrid, GEMM_THREADS, GEMM_SMEM>>>(bias);

    aggregate_kernel<<<N_NODES, 128>>>(out);
}

// round 7
// speedup vs baseline: 1.5081x; 1.5081x over previous
#include <cuda_runtime.h>
#include <cstdint>

// Problem constants (fixed shapes per reference)
#define N_NODES   8192
#define IN_F      1024
#define OUT_F     512
#define N_EDGES   262144
#define MASK_ROW_WORDS (N_NODES / 32)
#define MASK_WORDS     (N_NODES * MASK_ROW_WORDS)     // 8 MB
#define NBR_STRIDE 192

// Device-global scratch (allocation-free rule)
__device__ uint32_t g_mask[MASK_WORDS];
__device__ float    g_hidden[N_NODES * OUT_F];        // 16 MB
__device__ uint16_t g_nbr[N_NODES * NBR_STRIDE];
__device__ int      g_cnt[N_NODES];
__device__ int      g_is64;
// fp16 copies, packed half2 per u32 along K (k-contiguous)
__device__ uint32_t g_xh[N_NODES * (IN_F / 2)];       // 16 MB
__device__ uint32_t g_wh[OUT_F * (IN_F / 2)];         // 1 MB

// ---------------------------------------------------------------------------
// Graph preprocessing (unchanged from proven kernel)
// ---------------------------------------------------------------------------
__global__ void detect_dtype_kernel(const int* __restrict__ ei32) {
    int lane = threadIdx.x;
    int nonzero = 0;
    #pragma unroll
    for (int i = 0; i < 3; i++) {
        if (ei32[2 * (lane + 32 * i) + 1] != 0) nonzero = 1;
    }
    unsigned any = __ballot_sync(0xFFFFFFFFu, nonzero);
    if (lane == 0) g_is64 = (any == 0u) ? 1 : 0;
}

__global__ void zero_mask_kernel() {
    int idx = blockIdx.x * blockDim.x + threadIdx.x;
    uint4* p = reinterpret_cast<uint4*>(g_mask);
    int n4 = MASK_WORDS / 4;
    for (int i = idx; i < n4; i += gridDim.x * blockDim.x)
        p[i] = make_uint4(0u, 0u, 0u, 0u);
    if (idx < N_NODES) g_cnt[idx] = 0;
}

__global__ void build_mask_kernel(const int* __restrict__ ei32) {
    int e = blockIdx.x * blockDim.x + threadIdx.x;
    if (e >= N_EDGES) return;
    int src, dst;
    if (g_is64) {
        src = ei32[2 * e];
        dst = ei32[2 * (N_EDGES + e)];
    } else {
        src = ei32[e];
        dst = ei32[N_EDGES + e];
    }
    if ((unsigned)src >= N_NODES || (unsigned)dst >= N_NODES) return;
    uint32_t bit = 1u << (dst & 31);
    uint32_t old = atomicOr(&g_mask[src * MASK_ROW_WORDS + (dst >> 5)], bit);
    if (!(old & bit)) {
        int pos = atomicAdd(&g_cnt[src], 1);
        if (pos < NBR_STRIDE)
            g_nbr[src * NBR_STRIDE + pos] = (uint16_t)dst;
    }
}

// ---------------------------------------------------------------------------
// fp32 -> fp16 conversion (packed half2: low 16 bits = even k)
// ---------------------------------------------------------------------------
__global__ void convert_x_kernel(const float* __restrict__ x) {
    int n = N_NODES * (IN_F / 2);
    const float2* x2 = reinterpret_cast<const float2*>(x);
    for (int i = blockIdx.x * blockDim.x + threadIdx.x; i < n; i += gridDim.x * blockDim.x) {
        float2 v = x2[i];
        uint32_t h;
        asm("cvt.rn.f16x2.f32 %0, %1, %2;" : "=r"(h) : "f"(v.y), "f"(v.x));
        g_xh[i] = h;
    }
}

__global__ void convert_w_kernel(const float* __restrict__ W) {
    int n = OUT_F * (IN_F / 2);
    const float2* w2 = reinterpret_cast<const float2*>(W);
    for (int i = blockIdx.x * blockDim.x + threadIdx.x; i < n; i += gridDim.x * blockDim.x) {
        float2 v = w2[i];
        uint32_t h;
        asm("cvt.rn.f16x2.f32 %0, %1, %2;" : "=r"(h) : "f"(v.y), "f"(v.x));
        g_wh[i] = h;
    }
}

// ---------------------------------------------------------------------------
// mma.sync fp16 single-term GEMM:  hidden = x @ W^T + b
// Proven R5 geometry: CTA 128x64, BK=32, 256 threads, 8 warps (2m x 4n),
// warp tile 64x16; double-buffered cp.async; 80B-padded smem rows.
// 1/3 the MMA work of the 3-term bf16 split.
// ---------------------------------------------------------------------------
#define BM 128
#define BN 64
#define PAD_STRIDE 80          // bytes per 32-fp16 row (5 x 16B -> all banks)
#define ST_AH 0                // A: 128 * 80 = 10240
#define ST_BH 10240            // B: 64 * 80 = 5120
#define STAGE_SZ 15360
#define GEMM_SMEM (2 * STAGE_SZ)   // 30720 dynamic

__device__ __forceinline__ void cp16(uint32_t s, const void* g) {
    asm volatile("cp.async.cg.shared.global [%0], [%1], 16;" :: "r"(s), "l"(g) : "memory");
}

#define LDM_X4(r, addr) \
    asm volatile("ldmatrix.sync.aligned.m8n8.x4.shared.b16 {%0,%1,%2,%3}, [%4];" \
        : "=r"((r)[0]), "=r"((r)[1]), "=r"((r)[2]), "=r"((r)[3]) : "r"(addr))

#define MMA16816(c, a, b0, b1) \
    asm volatile("mma.sync.aligned.m16n8k16.row.col.f32.f16.f16.f32 " \
        "{%0,%1,%2,%3}, {%4,%5,%6,%7}, {%8,%9}, {%0,%1,%2,%3};" \
        : "+f"((c)[0]), "+f"((c)[1]), "+f"((c)[2]), "+f"((c)[3]) \
        : "r"((a)[0]), "r"((a)[1]), "r"((a)[2]), "r"((a)[3]), "r"(b0), "r"(b1))

__global__ __launch_bounds__(256, 2) void gemm_tc_kernel(const float* __restrict__ bias)
{
    extern __shared__ char smem[];
    const uint32_t sbase = (uint32_t)__cvta_generic_to_shared(smem);
    const int tid  = threadIdx.x;
    const int wid  = tid >> 5;
    const int lane = tid & 31;
    const int bm = blockIdx.y * BM;
    const int bn = blockIdx.x * BN;

    const int warp_m = wid >> 2;            // 0..1, 64 rows each
    const int warp_n = wid & 3;             // 0..3, 16 cols each

    float acc[4][2][4];
    #pragma unroll
    for (int i = 0; i < 4; i++)
        #pragma unroll
        for (int j = 0; j < 2; j++)
            #pragma unroll
            for (int k = 0; k < 4; k++) acc[i][j][k] = 0.f;

    // cp.async fill of one stage for K-chunk c (768 x 16B, 3 per thread)
    auto issue = [&](int stage, int c) {
        uint32_t st = sbase + stage * STAGE_SZ;
        #pragma unroll
        for (int t = 0; t < 3; t++) {
            int i = tid + t * 256;
            if (i < 512) {                               // A tile (128 rows)
                int row = i >> 2, seg = i & 3;
                const uint32_t* gsrc = g_xh
                    + (size_t)(bm + row) * (IN_F / 2) + c * 16 + seg * 4;
                cp16(st + ST_AH + row * PAD_STRIDE + seg * 16, gsrc);
            } else {                                     // B tile (64 rows)
                int j = i - 512;
                int row = j >> 2, seg = j & 3;
                const uint32_t* gsrc = g_wh
                    + (size_t)(bn + row) * (IN_F / 2) + c * 16 + seg * 4;
                cp16(st + ST_BH + row * PAD_STRIDE + seg * 16, gsrc);
            }
        }
        asm volatile("cp.async.commit_group;" ::: "memory");
    };

    // ldmatrix per-thread source rows (proven geometry)
    const int a_row  = warp_m * 64 + (lane & 15);     // + im*16
    const int a_half = lane >> 4;                     // k byte-half
    const int b_row  = warp_n * 16 + ((lane & 16) >> 1) + (lane & 7);
    const int b_half = (lane >> 3) & 1;

    issue(0, 0);

    const int NCHUNK = IN_F / 32;   // 32
    for (int c = 0; c < NCHUNK; c++) {
        if (c + 1 < NCHUNK) {
            issue((c + 1) & 1, c + 1);
            asm volatile("cp.async.wait_group 1;" ::: "memory");
        } else {
            asm volatile("cp.async.wait_group 0;" ::: "memory");
        }
        __syncthreads();

        const uint32_t st = sbase + (c & 1) * STAGE_SZ;
        #pragma unroll
        for (int ks = 0; ks < 2; ks++) {
            const int kb = ks * 32;                   // 16 fp16 = 32 bytes
            uint32_t ah[4][4];
            #pragma unroll
            for (int im = 0; im < 4; im++) {
                uint32_t addr = st + ST_AH + (a_row + im * 16) * PAD_STRIDE + kb + a_half * 16;
                LDM_X4(ah[im], addr);
            }
            uint32_t bh[4];
            {
                uint32_t addr = st + ST_BH + b_row * PAD_STRIDE + kb + b_half * 16;
                LDM_X4(bh, addr);
            }
            #pragma unroll
            for (int im = 0; im < 4; im++) {
                #pragma unroll
                for (int in = 0; in < 2; in++) {
                    MMA16816(acc[im][in], ah[im], bh[in * 2], bh[in * 2 + 1]);
                }
            }
        }
        __syncthreads();
    }

    // Epilogue: add bias, store fp32 hidden
    const int er = lane >> 2;
    const int ec = (lane & 3) * 2;
    #pragma unroll
    for (int im = 0; im < 4; im++) {
        int r0 = bm + warp_m * 64 + im * 16 + er;
        #pragma unroll
        for (int in = 0; in < 2; in++) {
            int col = bn + warp_n * 16 + in * 8 + ec;
            float b0 = __ldg(&bias[col]);
            float b1 = __ldg(&bias[col + 1]);
            float2 v0 = make_float2(acc[im][in][0] + b0, acc[im][in][1] + b1);
            float2 v1 = make_float2(acc[im][in][2] + b0, acc[im][in][3] + b1);
            *reinterpret_cast<float2*>(&g_hidden[(size_t)r0 * OUT_F + col]) = v0;
            *reinterpret_cast<float2*>(&g_hidden[(size_t)(r0 + 8) * OUT_F + col]) = v1;
        }
    }
}

// ---------------------------------------------------------------------------
// out[row] = relu( sum_{j in nbr[row]} hidden[j] )  (unchanged)
// ---------------------------------------------------------------------------
__global__ __launch_bounds__(128) void aggregate_kernel(float* __restrict__ out) {
    __shared__ uint16_t s_nbr[NBR_STRIDE];
    __shared__ int s_deg;

    const int row = blockIdx.x;
    const int col = threadIdx.x;

    if (col == 0) s_deg = min(g_cnt[row], NBR_STRIDE);
    __syncthreads();
    const int deg = s_deg;
    for (int i = col; i < deg; i += 128)
        s_nbr[i] = g_nbr[row * NBR_STRIDE + i];
    __syncthreads();

    const float4* H = reinterpret_cast<const float4*>(g_hidden);

    float4 a0 = make_float4(0.f, 0.f, 0.f, 0.f);
    float4 a1 = make_float4(0.f, 0.f, 0.f, 0.f);
    float4 a2 = make_float4(0.f, 0.f, 0.f, 0.f);
    float4 a3 = make_float4(0.f, 0.f, 0.f, 0.f);

    int i = 0;
    for (; i + 4 <= deg; i += 4) {
        int j0 = s_nbr[i + 0], j1 = s_nbr[i + 1];
        int j2 = s_nbr[i + 2], j3 = s_nbr[i + 3];
        float4 v0 = H[j0 * 128 + col];
        float4 v1 = H[j1 * 128 + col];
        float4 v2 = H[j2 * 128 + col];
        float4 v3 = H[j3 * 128 + col];
        a0.x += v0.x; a0.y += v0.y; a0.z += v0.z; a0.w += v0.w;
        a1.x += v1.x; a1.y += v1.y; a1.z += v1.z; a1.w += v1.w;
        a2.x += v2.x; a2.y += v2.y; a2.z += v2.z; a2.w += v2.w;
        a3.x += v3.x; a3.y += v3.y; a3.z += v3.z; a3.w += v3.w;
    }
    for (; i < deg; i++) {
        int j = s_nbr[i];
        float4 v = H[j * 128 + col];
        a0.x += v.x; a0.y += v.y; a0.z += v.z; a0.w += v.w;
    }

    float4 r;
    r.x = fmaxf(a0.x + a1.x + a2.x + a3.x, 0.f);
    r.y = fmaxf(a0.y + a1.y + a2.y + a3.y, 0.f);
    r.z = fmaxf(a0.z + a1.z + a2.z + a3.z, 0.f);
    r.w = fmaxf(a0.w + a1.w + a2.w + a3.w, 0.f);
    reinterpret_cast<float4*>(out)[row * 128 + col] = r;
}

// ---------------------------------------------------------------------------
// Launch
// ---------------------------------------------------------------------------
extern "C" void kernel_launch(void* const* d_in, const int* in_sizes, int n_in,
                              void* d_out, int out_size)
{
    const float* x    = (const float*)d_in[0];
    const float* W    = (const float*)d_in[1];
    const float* bias = (const float*)d_in[2];
    const int*   ei   = (const int*)d_in[3];
    float*       out  = (float*)d_out;

    (void)in_sizes; (void)n_in; (void)out_size;

    cudaFuncSetAttribute(gemm_tc_kernel,
                         cudaFuncAttributeMaxDynamicSharedMemorySize, GEMM_SMEM);

    detect_dtype_kernel<<<1, 32>>>(ei);
    zero_mask_kernel<<<1024, 256>>>();
    build_mask_kernel<<<N_EDGES / 256, 256>>>(ei);

    convert_x_kernel<<<2048, 256>>>(x);
    convert_w_kernel<<<512, 256>>>(W);

    dim3 ggrid(OUT_F / BN, N_NODES / BM);   // (8, 64)
    gemm_tc_kernel<<<ggrid, 256, GEMM_SMEM>>>(bias);

    aggregate_kernel<<<N_NODES, 128>>>(out);
}

// round 8
// speedup vs baseline: 1.6480x; 1.0927x over previous
#include <cuda_runtime.h>
#include <cuda_fp16.h>
#include <cstdint>

// Problem constants (fixed shapes per reference)
#define N_NODES   8192
#define IN_F      1024
#define OUT_F     512
#define N_EDGES   262144
#define MASK_ROW_WORDS (N_NODES / 32)
#define MASK_WORDS     (N_NODES * MASK_ROW_WORDS)     // 8 MB
#define NBR_STRIDE 192

// Device-global scratch (allocation-free rule)
__device__ uint32_t g_mask[MASK_WORDS];
__device__ uint32_t g_hidden[N_NODES * (OUT_F / 2)];  // fp16 half2-packed, 8 MB
__device__ uint16_t g_nbr[N_NODES * NBR_STRIDE];
__device__ int      g_cnt[N_NODES];
__device__ int      g_is64;
// fp16 copies, packed half2 per u32 along K (k-contiguous)
__device__ uint32_t g_xh[N_NODES * (IN_F / 2)];       // 16 MB
__device__ uint32_t g_wh[OUT_F * (IN_F / 2)];         // 1 MB

// ---------------------------------------------------------------------------
// Graph preprocessing (unchanged)
// ---------------------------------------------------------------------------
__global__ void detect_dtype_kernel(const int* __restrict__ ei32) {
    int lane = threadIdx.x;
    int nonzero = 0;
    #pragma unroll
    for (int i = 0; i < 3; i++) {
        if (ei32[2 * (lane + 32 * i) + 1] != 0) nonzero = 1;
    }
    unsigned any = __ballot_sync(0xFFFFFFFFu, nonzero);
    if (lane == 0) g_is64 = (any == 0u) ? 1 : 0;
}

__global__ void zero_mask_kernel() {
    int idx = blockIdx.x * blockDim.x + threadIdx.x;
    uint4* p = reinterpret_cast<uint4*>(g_mask);
    int n4 = MASK_WORDS / 4;
    for (int i = idx; i < n4; i += gridDim.x * blockDim.x)
        p[i] = make_uint4(0u, 0u, 0u, 0u);
    if (idx < N_NODES) g_cnt[idx] = 0;
}

__global__ void build_mask_kernel(const int* __restrict__ ei32) {
    int e = blockIdx.x * blockDim.x + threadIdx.x;
    if (e >= N_EDGES) return;
    int src, dst;
    if (g_is64) {
        src = ei32[2 * e];
        dst = ei32[2 * (N_EDGES + e)];
    } else {
        src = ei32[e];
        dst = ei32[N_EDGES + e];
    }
    if ((unsigned)src >= N_NODES || (unsigned)dst >= N_NODES) return;
    uint32_t bit = 1u << (dst & 31);
    uint32_t old = atomicOr(&g_mask[src * MASK_ROW_WORDS + (dst >> 5)], bit);
    if (!(old & bit)) {
        int pos = atomicAdd(&g_cnt[src], 1);
        if (pos < NBR_STRIDE)
            g_nbr[src * NBR_STRIDE + pos] = (uint16_t)dst;
    }
}

// ---------------------------------------------------------------------------
// fp32 -> fp16 conversion, float4-vectorized
// ---------------------------------------------------------------------------
__global__ void convert_x_kernel(const float* __restrict__ x) {
    int n = N_NODES * (IN_F / 4);                     // float4 count
    const float4* x4 = reinterpret_cast<const float4*>(x);
    uint2* dst = reinterpret_cast<uint2*>(g_xh);
    for (int i = blockIdx.x * blockDim.x + threadIdx.x; i < n; i += gridDim.x * blockDim.x) {
        float4 v = x4[i];
        uint2 h;
        asm("cvt.rn.f16x2.f32 %0, %1, %2;" : "=r"(h.x) : "f"(v.y), "f"(v.x));
        asm("cvt.rn.f16x2.f32 %0, %1, %2;" : "=r"(h.y) : "f"(v.w), "f"(v.z));
        dst[i] = h;
    }
}

__global__ void convert_w_kernel(const float* __restrict__ W) {
    int n = OUT_F * (IN_F / 4);
    const float4* w4 = reinterpret_cast<const float4*>(W);
    uint2* dst = reinterpret_cast<uint2*>(g_wh);
    for (int i = blockIdx.x * blockDim.x + threadIdx.x; i < n; i += gridDim.x * blockDim.x) {
        float4 v = w4[i];
        uint2 h;
        asm("cvt.rn.f16x2.f32 %0, %1, %2;" : "=r"(h.x) : "f"(v.y), "f"(v.x));
        asm("cvt.rn.f16x2.f32 %0, %1, %2;" : "=r"(h.y) : "f"(v.w), "f"(v.z));
        dst[i] = h;
    }
}

// ---------------------------------------------------------------------------
// mma.sync fp16 GEMM:  hidden = fp16(x @ W^T + b)
// Proven geometry: CTA 128x64, BK=32, 256 threads, 8 warps (2m x 4n).
// ---------------------------------------------------------------------------
#define BM 128
#define BN 64
#define PAD_STRIDE 80
#define ST_AH 0
#define ST_BH 10240
#define STAGE_SZ 15360
#define GEMM_SMEM (2 * STAGE_SZ)

__device__ __forceinline__ void cp16(uint32_t s, const void* g) {
    asm volatile("cp.async.cg.shared.global [%0], [%1], 16;" :: "r"(s), "l"(g) : "memory");
}

#define LDM_X4(r, addr) \
    asm volatile("ldmatrix.sync.aligned.m8n8.x4.shared.b16 {%0,%1,%2,%3}, [%4];" \
        : "=r"((r)[0]), "=r"((r)[1]), "=r"((r)[2]), "=r"((r)[3]) : "r"(addr))

#define MMA16816(c, a, b0, b1) \
    asm volatile("mma.sync.aligned.m16n8k16.row.col.f32.f16.f16.f32 " \
        "{%0,%1,%2,%3}, {%4,%5,%6,%7}, {%8,%9}, {%0,%1,%2,%3};" \
        : "+f"((c)[0]), "+f"((c)[1]), "+f"((c)[2]), "+f"((c)[3]) \
        : "r"((a)[0]), "r"((a)[1]), "r"((a)[2]), "r"((a)[3]), "r"(b0), "r"(b1))

__global__ __launch_bounds__(256, 2) void gemm_tc_kernel(const float* __restrict__ bias)
{
    extern __shared__ char smem[];
    const uint32_t sbase = (uint32_t)__cvta_generic_to_shared(smem);
    const int tid  = threadIdx.x;
    const int wid  = tid >> 5;
    const int lane = tid & 31;
    const int bm = blockIdx.y * BM;
    const int bn = blockIdx.x * BN;

    const int warp_m = wid >> 2;
    const int warp_n = wid & 3;

    float acc[4][2][4];
    #pragma unroll
    for (int i = 0; i < 4; i++)
        #pragma unroll
        for (int j = 0; j < 2; j++)
            #pragma unroll
            for (int k = 0; k < 4; k++) acc[i][j][k] = 0.f;

    auto issue = [&](int stage, int c) {
        uint32_t st = sbase + stage * STAGE_SZ;
        #pragma unroll
        for (int t = 0; t < 3; t++) {
            int i = tid + t * 256;
            if (i < 512) {
                int row = i >> 2, seg = i & 3;
                const uint32_t* gsrc = g_xh
                    + (size_t)(bm + row) * (IN_F / 2) + c * 16 + seg * 4;
                cp16(st + ST_AH + row * PAD_STRIDE + seg * 16, gsrc);
            } else {
                int j = i - 512;
                int row = j >> 2, seg = j & 3;
                const uint32_t* gsrc = g_wh
                    + (size_t)(bn + row) * (IN_F / 2) + c * 16 + seg * 4;
                cp16(st + ST_BH + row * PAD_STRIDE + seg * 16, gsrc);
            }
        }
        asm volatile("cp.async.commit_group;" ::: "memory");
    };

    const int a_row  = warp_m * 64 + (lane & 15);
    const int a_half = lane >> 4;
    const int b_row  = warp_n * 16 + ((lane & 16) >> 1) + (lane & 7);
    const int b_half = (lane >> 3) & 1;

    issue(0, 0);

    const int NCHUNK = IN_F / 32;   // 32
    for (int c = 0; c < NCHUNK; c++) {
        if (c + 1 < NCHUNK) {
            issue((c + 1) & 1, c + 1);
            asm volatile("cp.async.wait_group 1;" ::: "memory");
        } else {
            asm volatile("cp.async.wait_group 0;" ::: "memory");
        }
        __syncthreads();

        const uint32_t st = sbase + (c & 1) * STAGE_SZ;
        #pragma unroll
        for (int ks = 0; ks < 2; ks++) {
            const int kb = ks * 32;
            uint32_t ah[4][4];
            #pragma unroll
            for (int im = 0; im < 4; im++) {
                uint32_t addr = st + ST_AH + (a_row + im * 16) * PAD_STRIDE + kb + a_half * 16;
                LDM_X4(ah[im], addr);
            }
            uint32_t bh[4];
            {
                uint32_t addr = st + ST_BH + b_row * PAD_STRIDE + kb + b_half * 16;
                LDM_X4(bh, addr);
            }
            #pragma unroll
            for (int im = 0; im < 4; im++) {
                #pragma unroll
                for (int in = 0; in < 2; in++) {
                    MMA16816(acc[im][in], ah[im], bh[in * 2], bh[in * 2 + 1]);
                }
            }
        }
        __syncthreads();
    }

    // Epilogue: add bias, convert to half2, store packed fp16 hidden
    const int er = lane >> 2;
    const int ec = (lane & 3) * 2;
    #pragma unroll
    for (int im = 0; im < 4; im++) {
        int r0 = bm + warp_m * 64 + im * 16 + er;
        #pragma unroll
        for (int in = 0; in < 2; in++) {
            int col = bn + warp_n * 16 + in * 8 + ec;     // even
            float b0 = __ldg(&bias[col]);
            float b1 = __ldg(&bias[col + 1]);
            uint32_t h0, h1;
            asm("cvt.rn.f16x2.f32 %0, %1, %2;" : "=r"(h0)
                : "f"(acc[im][in][1] + b1), "f"(acc[im][in][0] + b0));
            asm("cvt.rn.f16x2.f32 %0, %1, %2;" : "=r"(h1)
                : "f"(acc[im][in][3] + b1), "f"(acc[im][in][2] + b0));
            g_hidden[(size_t)r0 * (OUT_F / 2) + (col >> 1)] = h0;
            g_hidden[(size_t)(r0 + 8) * (OUT_F / 2) + (col >> 1)] = h1;
        }
    }
}

// ---------------------------------------------------------------------------
// out[row] = relu( sum_{j in nbr[row]} hidden_fp16[j] )  fp32 accumulation.
// 1 block/row, 128 threads; each thread covers 4 features (one uint2 = 4 halves).
// L2 traffic halved vs fp32 hidden: ~256MB -> ~23us floor.
// ---------------------------------------------------------------------------
__global__ __launch_bounds__(128) void aggregate_kernel(float* __restrict__ out) {
    __shared__ uint16_t s_nbr[NBR_STRIDE];
    __shared__ int s_deg;

    const int row = blockIdx.x;
    const int t   = threadIdx.x;        // 0..127, 4 features each

    if (t == 0) s_deg = min(g_cnt[row], NBR_STRIDE);
    __syncthreads();
    const int deg = s_deg;
    for (int i = t; i < deg; i += 128)
        s_nbr[i] = g_nbr[row * NBR_STRIDE + i];
    __syncthreads();

    const uint2* H = reinterpret_cast<const uint2*>(g_hidden);  // 128 uint2 per row

    float4 a0 = make_float4(0.f, 0.f, 0.f, 0.f);
    float4 a1 = make_float4(0.f, 0.f, 0.f, 0.f);
    float4 a2 = make_float4(0.f, 0.f, 0.f, 0.f);
    float4 a3 = make_float4(0.f, 0.f, 0.f, 0.f);

    auto acc4 = [](float4& a, uint2 u) {
        float2 lo = __half22float2(*reinterpret_cast<__half2*>(&u.x));
        float2 hi = __half22float2(*reinterpret_cast<__half2*>(&u.y));
        a.x += lo.x; a.y += lo.y; a.z += hi.x; a.w += hi.y;
    };

    int i = 0;
    for (; i + 4 <= deg; i += 4) {
        int j0 = s_nbr[i + 0], j1 = s_nbr[i + 1];
        int j2 = s_nbr[i + 2], j3 = s_nbr[i + 3];
        uint2 u0 = H[j0 * 128 + t];
        uint2 u1 = H[j1 * 128 + t];
        uint2 u2 = H[j2 * 128 + t];
        uint2 u3 = H[j3 * 128 + t];
        acc4(a0, u0); acc4(a1, u1); acc4(a2, u2); acc4(a3, u3);
    }
    for (; i < deg; i++) {
        uint2 u = H[s_nbr[i] * 128 + t];
        acc4(a0, u);
    }

    float4 r;
    r.x = fmaxf(a0.x + a1.x + a2.x + a3.x, 0.f);
    r.y = fmaxf(a0.y + a1.y + a2.y + a3.y, 0.f);
    r.z = fmaxf(a0.z + a1.z + a2.z + a3.z, 0.f);
    r.w = fmaxf(a0.w + a1.w + a2.w + a3.w, 0.f);
    reinterpret_cast<float4*>(out)[row * 128 + t] = r;
}

// ---------------------------------------------------------------------------
// Launch
// ---------------------------------------------------------------------------
extern "C" void kernel_launch(void* const* d_in, const int* in_sizes, int n_in,
                              void* d_out, int out_size)
{
    const float* x    = (const float*)d_in[0];
    const float* W    = (const float*)d_in[1];
    const float* bias = (const float*)d_in[2];
    const int*   ei   = (const int*)d_in[3];
    float*       out  = (float*)d_out;

    (void)in_sizes; (void)n_in; (void)out_size;

    cudaFuncSetAttribute(gemm_tc_kernel,
                         cudaFuncAttributeMaxDynamicSharedMemorySize, GEMM_SMEM);

    detect_dtype_kernel<<<1, 32>>>(ei);
    zero_mask_kernel<<<1024, 256>>>();
    build_mask_kernel<<<N_EDGES / 256, 256>>>(ei);

    convert_x_kernel<<<2048, 256>>>(x);
    convert_w_kernel<<<512, 256>>>(W);

    dim3 ggrid(OUT_F / BN, N_NODES / BM);   // (8, 64)
    gemm_tc_kernel<<<ggrid, 256, GEMM_SMEM>>>(bias);

    aggregate_kernel<<<N_NODES, 128>>>(out);
}

// round 9
// speedup vs baseline: 1.7334x; 1.0519x over previous
#include <cuda_runtime.h>
#include <cuda_fp16.h>
#include <cstdint>

// Problem constants (fixed shapes per reference)
#define N_NODES   8192
#define IN_F      1024
#define OUT_F     512
#define N_EDGES   262144
#define MASK_ROW_WORDS (N_NODES / 32)
#define MASK_WORDS     (N_NODES * MASK_ROW_WORDS)     // 8 MB
#define NBR_STRIDE 192

// Device-global scratch (allocation-free rule)
__device__ uint32_t g_mask[MASK_WORDS];
__device__ uint32_t g_hidden[N_NODES * (OUT_F / 2)];  // fp16 half2-packed, 8 MB
__device__ uint16_t g_nbr[N_NODES * NBR_STRIDE];
__device__ int      g_cnt[N_NODES];
__device__ int      g_is64;
// fp16 copies, packed half2 per u32 along K (k-contiguous)
__device__ uint32_t g_xh[N_NODES * (IN_F / 2)];       // 16 MB
__device__ uint32_t g_wh[OUT_F * (IN_F / 2)];         // 1 MB

// ---------------------------------------------------------------------------
// Kernel A (stream 0): zero mask + counters; block 0 also detects edge dtype.
// ---------------------------------------------------------------------------
__global__ void prep_kernel(const int* __restrict__ ei32) {
    int idx = blockIdx.x * blockDim.x + threadIdx.x;

    if (blockIdx.x == 0 && threadIdx.x < 32) {
        int lane = threadIdx.x;
        int nonzero = 0;
        #pragma unroll
        for (int i = 0; i < 3; i++) {
            if (ei32[2 * (lane + 32 * i) + 1] != 0) nonzero = 1;
        }
        unsigned any = __ballot_sync(0xFFFFFFFFu, nonzero);
        if (lane == 0) g_is64 = (any == 0u) ? 1 : 0;
    }

    uint4* p = reinterpret_cast<uint4*>(g_mask);
    int n4 = MASK_WORDS / 4;
    for (int i = idx; i < n4; i += gridDim.x * blockDim.x)
        p[i] = make_uint4(0u, 0u, 0u, 0u);
    if (idx < N_NODES) g_cnt[idx] = 0;
}

// ---------------------------------------------------------------------------
// Kernel B (stream 0): build deduped neighbor lists (set semantics via OR)
// ---------------------------------------------------------------------------
__global__ void build_mask_kernel(const int* __restrict__ ei32) {
    int e = blockIdx.x * blockDim.x + threadIdx.x;
    if (e >= N_EDGES) return;
    int src, dst;
    if (g_is64) {
        src = ei32[2 * e];
        dst = ei32[2 * (N_EDGES + e)];
    } else {
        src = ei32[e];
        dst = ei32[N_EDGES + e];
    }
    if ((unsigned)src >= N_NODES || (unsigned)dst >= N_NODES) return;
    uint32_t bit = 1u << (dst & 31);
    uint32_t old = atomicOr(&g_mask[src * MASK_ROW_WORDS + (dst >> 5)], bit);
    if (!(old & bit)) {
        int pos = atomicAdd(&g_cnt[src], 1);
        if (pos < NBR_STRIDE)
            g_nbr[src * NBR_STRIDE + pos] = (uint16_t)dst;
    }
}

// ---------------------------------------------------------------------------
// Kernel C (stream 1): fp32 -> fp16 conversion for x AND W, float4-vectorized
// ---------------------------------------------------------------------------
__global__ void convert_kernel(const float* __restrict__ x, const float* __restrict__ W) {
    const int nx = N_NODES * (IN_F / 4);
    const int nw = OUT_F * (IN_F / 4);
    const float4* x4 = reinterpret_cast<const float4*>(x);
    const float4* w4 = reinterpret_cast<const float4*>(W);
    uint2* xdst = reinterpret_cast<uint2*>(g_xh);
    uint2* wdst = reinterpret_cast<uint2*>(g_wh);
    for (int i = blockIdx.x * blockDim.x + threadIdx.x; i < nx + nw;
         i += gridDim.x * blockDim.x) {
        float4 v = (i < nx) ? x4[i] : w4[i - nx];
        uint2 h;
        asm("cvt.rn.f16x2.f32 %0, %1, %2;" : "=r"(h.x) : "f"(v.y), "f"(v.x));
        asm("cvt.rn.f16x2.f32 %0, %1, %2;" : "=r"(h.y) : "f"(v.w), "f"(v.z));
        if (i < nx) xdst[i] = h; else wdst[i - nx] = h;
    }
}

// ---------------------------------------------------------------------------
// mma.sync fp16 GEMM:  hidden = fp16(x @ W^T + b)
// Proven geometry: CTA 128x64, BK=32, 256 threads, 8 warps (2m x 4n).
// ---------------------------------------------------------------------------
#define BM 128
#define BN 64
#define PAD_STRIDE 80
#define ST_AH 0
#define ST_BH 10240
#define STAGE_SZ 15360
#define GEMM_SMEM (2 * STAGE_SZ)

__device__ __forceinline__ void cp16(uint32_t s, const void* g) {
    asm volatile("cp.async.cg.shared.global [%0], [%1], 16;" :: "r"(s), "l"(g) : "memory");
}

#define LDM_X4(r, addr) \
    asm volatile("ldmatrix.sync.aligned.m8n8.x4.shared.b16 {%0,%1,%2,%3}, [%4];" \
        : "=r"((r)[0]), "=r"((r)[1]), "=r"((r)[2]), "=r"((r)[3]) : "r"(addr))

#define MMA16816(c, a, b0, b1) \
    asm volatile("mma.sync.aligned.m16n8k16.row.col.f32.f16.f16.f32 " \
        "{%0,%1,%2,%3}, {%4,%5,%6,%7}, {%8,%9}, {%0,%1,%2,%3};" \
        : "+f"((c)[0]), "+f"((c)[1]), "+f"((c)[2]), "+f"((c)[3]) \
        : "r"((a)[0]), "r"((a)[1]), "r"((a)[2]), "r"((a)[3]), "r"(b0), "r"(b1))

__global__ __launch_bounds__(256, 2) void gemm_tc_kernel(const float* __restrict__ bias)
{
    extern __shared__ char smem[];
    const uint32_t sbase = (uint32_t)__cvta_generic_to_shared(smem);
    const int tid  = threadIdx.x;
    const int wid  = tid >> 5;
    const int lane = tid & 31;
    const int bm = blockIdx.y * BM;
    const int bn = blockIdx.x * BN;

    const int warp_m = wid >> 2;
    const int warp_n = wid & 3;

    float acc[4][2][4];
    #pragma unroll
    for (int i = 0; i < 4; i++)
        #pragma unroll
        for (int j = 0; j < 2; j++)
            #pragma unroll
            for (int k = 0; k < 4; k++) acc[i][j][k] = 0.f;

    auto issue = [&](int stage, int c) {
        uint32_t st = sbase + stage * STAGE_SZ;
        #pragma unroll
        for (int t = 0; t < 3; t++) {
            int i = tid + t * 256;
            if (i < 512) {
                int row = i >> 2, seg = i & 3;
                const uint32_t* gsrc = g_xh
                    + (size_t)(bm + row) * (IN_F / 2) + c * 16 + seg * 4;
                cp16(st + ST_AH + row * PAD_STRIDE + seg * 16, gsrc);
            } else {
                int j = i - 512;
                int row = j >> 2, seg = j & 3;
                const uint32_t* gsrc = g_wh
                    + (size_t)(bn + row) * (IN_F / 2) + c * 16 + seg * 4;
                cp16(st + ST_BH + row * PAD_STRIDE + seg * 16, gsrc);
            }
        }
        asm volatile("cp.async.commit_group;" ::: "memory");
    };

    const int a_row  = warp_m * 64 + (lane & 15);
    const int a_half = lane >> 4;
    const int b_row  = warp_n * 16 + ((lane & 16) >> 1) + (lane & 7);
    const int b_half = (lane >> 3) & 1;

    issue(0, 0);

    const int NCHUNK = IN_F / 32;   // 32
    for (int c = 0; c < NCHUNK; c++) {
        if (c + 1 < NCHUNK) {
            issue((c + 1) & 1, c + 1);
            asm volatile("cp.async.wait_group 1;" ::: "memory");
        } else {
            asm volatile("cp.async.wait_group 0;" ::: "memory");
        }
        __syncthreads();

        const uint32_t st = sbase + (c & 1) * STAGE_SZ;
        #pragma unroll
        for (int ks = 0; ks < 2; ks++) {
            const int kb = ks * 32;
            uint32_t ah[4][4];
            #pragma unroll
            for (int im = 0; im < 4; im++) {
                uint32_t addr = st + ST_AH + (a_row + im * 16) * PAD_STRIDE + kb + a_half * 16;
                LDM_X4(ah[im], addr);
            }
            uint32_t bh[4];
            {
                uint32_t addr = st + ST_BH + b_row * PAD_STRIDE + kb + b_half * 16;
                LDM_X4(bh, addr);
            }
            #pragma unroll
            for (int im = 0; im < 4; im++) {
                #pragma unroll
                for (int in = 0; in < 2; in++) {
                    MMA16816(acc[im][in], ah[im], bh[in * 2], bh[in * 2 + 1]);
                }
            }
        }
        __syncthreads();
    }

    // Epilogue: add bias, convert to half2, store packed fp16 hidden
    const int er = lane >> 2;
    const int ec = (lane & 3) * 2;
    #pragma unroll
    for (int im = 0; im < 4; im++) {
        int r0 = bm + warp_m * 64 + im * 16 + er;
        #pragma unroll
        for (int in = 0; in < 2; in++) {
            int col = bn + warp_n * 16 + in * 8 + ec;
            float b0 = __ldg(&bias[col]);
            float b1 = __ldg(&bias[col + 1]);
            uint32_t h0, h1;
            asm("cvt.rn.f16x2.f32 %0, %1, %2;" : "=r"(h0)
                : "f"(acc[im][in][1] + b1), "f"(acc[im][in][0] + b0));
            asm("cvt.rn.f16x2.f32 %0, %1, %2;" : "=r"(h1)
                : "f"(acc[im][in][3] + b1), "f"(acc[im][in][2] + b0));
            g_hidden[(size_t)r0 * (OUT_F / 2) + (col >> 1)] = h0;
            g_hidden[(size_t)(r0 + 8) * (OUT_F / 2) + (col >> 1)] = h1;
        }
    }
}

// ---------------------------------------------------------------------------
// out[row] = relu( sum_{j in nbr[row]} hidden_fp16[j] )  fp32 accumulation.
// 1 block/row, 128 threads x (uint2 = 4 halves); 8 independent accumulators.
// ---------------------------------------------------------------------------
__global__ __launch_bounds__(128) void aggregate_kernel(float* __restrict__ out) {
    __shared__ uint16_t s_nbr[NBR_STRIDE];
    __shared__ int s_deg;

    const int row = blockIdx.x;
    const int t   = threadIdx.x;

    if (t == 0) s_deg = min(g_cnt[row], NBR_STRIDE);
    __syncthreads();
    const int deg = s_deg;
    for (int i = t; i < deg; i += 128)
        s_nbr[i] = g_nbr[row * NBR_STRIDE + i];
    __syncthreads();

    const uint2* H = reinterpret_cast<const uint2*>(g_hidden);

    float4 a[8];
    #pragma unroll
    for (int k = 0; k < 8; k++) a[k] = make_float4(0.f, 0.f, 0.f, 0.f);

    auto acc4 = [](float4& a, uint2 u) {
        float2 lo = __half22float2(*reinterpret_cast<__half2*>(&u.x));
        float2 hi = __half22float2(*reinterpret_cast<__half2*>(&u.y));
        a.x += lo.x; a.y += lo.y; a.z += hi.x; a.w += hi.y;
    };

    int i = 0;
    for (; i + 8 <= deg; i += 8) {
        uint2 u[8];
        #pragma unroll
        for (int k = 0; k < 8; k++) u[k] = H[s_nbr[i + k] * 128 + t];
        #pragma unroll
        for (int k = 0; k < 8; k++) acc4(a[k], u[k]);
    }
    for (; i < deg; i++) {
        uint2 u = H[s_nbr[i] * 128 + t];
        acc4(a[0], u);
    }

    #pragma unroll
    for (int k = 4; k > 0; k >>= 1)
        #pragma unroll
        for (int j = 0; j < k; j++) {
            a[j].x += a[j + k].x; a[j].y += a[j + k].y;
            a[j].z += a[j + k].z; a[j].w += a[j + k].w;
        }

    float4 r;
    r.x = fmaxf(a[0].x, 0.f);
    r.y = fmaxf(a[0].y, 0.f);
    r.z = fmaxf(a[0].z, 0.f);
    r.w = fmaxf(a[0].w, 0.f);
    reinterpret_cast<float4*>(out)[row * 128 + t] = r;
}

// ---------------------------------------------------------------------------
// Launch: fork-join — converts on s1 overlap mask prep on stream 0.
// Streams/events created on first (non-captured) correctness call; reused in
// capture, where event record/wait become graph dependencies.
// ---------------------------------------------------------------------------
extern "C" void kernel_launch(void* const* d_in, const int* in_sizes, int n_in,
                              void* d_out, int out_size)
{
    const float* x    = (const float*)d_in[0];
    const float* W    = (const float*)d_in[1];
    const float* bias = (const float*)d_in[2];
    const int*   ei   = (const int*)d_in[3];
    float*       out  = (float*)d_out;

    (void)in_sizes; (void)n_in; (void)out_size;

    static cudaStream_t s1;
    static cudaEvent_t ev_fork, ev_conv;
    static bool init = false;
    if (!init) {
        cudaStreamCreateWithFlags(&s1, cudaStreamNonBlocking);
        cudaEventCreateWithFlags(&ev_fork, cudaEventDisableTiming);
        cudaEventCreateWithFlags(&ev_conv, cudaEventDisableTiming);
        cudaFuncSetAttribute(gemm_tc_kernel,
                             cudaFuncAttributeMaxDynamicSharedMemorySize, GEMM_SMEM);
        init = true;
    }

    // fork: converts run on s1 concurrently with mask prep on stream 0
    cudaEventRecord(ev_fork, 0);
    cudaStreamWaitEvent(s1, ev_fork, 0);
    convert_kernel<<<2048, 256, 0, s1>>>(x, W);
    cudaEventRecord(ev_conv, s1);

    prep_kernel<<<1024, 256>>>(ei);
    build_mask_kernel<<<N_EDGES / 256, 256>>>(ei);

    // join: GEMM needs converts done
    cudaStreamWaitEvent(0, ev_conv, 0);

    dim3 ggrid(OUT_F / BN, N_NODES / BM);   // (8, 64)
    gemm_tc_kernel<<<ggrid, 256, GEMM_SMEM>>>(bias);

    aggregate_kernel<<<N_NODES, 128>>>(out);
}

// round 11
// speedup vs baseline: 2.0697x; 1.1940x over previous
#include <cuda_runtime.h>
#include <cuda_fp16.h>
#include <cstdint>

// Problem constants (fixed shapes per reference)
#define N_NODES   8192
#define IN_F      1024
#define OUT_F     512
#define N_EDGES   262144
#define MASK_ROW_WORDS (N_NODES / 32)
#define MASK_WORDS     (N_NODES * MASK_ROW_WORDS)     // 8 MB
#define NBR_STRIDE 192

// Device-global scratch (allocation-free rule)
__device__ uint32_t g_mask[MASK_WORDS];
__device__ uint32_t g_hidden[N_NODES * (OUT_F / 2)];  // fp16 half2-packed, 8 MB
__device__ uint16_t g_nbr[N_NODES * NBR_STRIDE];
__device__ int      g_cnt[N_NODES];
__device__ int      g_is64;
// fp16 copies, packed half2 per u32 along K (k-contiguous)
__device__ uint32_t g_xh[N_NODES * (IN_F / 2)];       // 16 MB
__device__ uint32_t g_wh[OUT_F * (IN_F / 2)];         // 1 MB

// ---------------------------------------------------------------------------
// Kernel A (stream 0): zero mask + counters; block 0 also detects edge dtype.
// ---------------------------------------------------------------------------
__global__ void prep_kernel(const int* __restrict__ ei32) {
    int idx = blockIdx.x * blockDim.x + threadIdx.x;

    if (blockIdx.x == 0 && threadIdx.x < 32) {
        int lane = threadIdx.x;
        int nonzero = 0;
        #pragma unroll
        for (int i = 0; i < 3; i++) {
            if (ei32[2 * (lane + 32 * i) + 1] != 0) nonzero = 1;
        }
        unsigned any = __ballot_sync(0xFFFFFFFFu, nonzero);
        if (lane == 0) g_is64 = (any == 0u) ? 1 : 0;
    }

    uint4* p = reinterpret_cast<uint4*>(g_mask);
    int n4 = MASK_WORDS / 4;
    for (int i = idx; i < n4; i += gridDim.x * blockDim.x)
        p[i] = make_uint4(0u, 0u, 0u, 0u);
    if (idx < N_NODES) g_cnt[idx] = 0;
}

// ---------------------------------------------------------------------------
// Kernel B (stream 0): build deduped neighbor lists (set semantics via OR)
// ---------------------------------------------------------------------------
__global__ void build_mask_kernel(const int* __restrict__ ei32) {
    int e = blockIdx.x * blockDim.x + threadIdx.x;
    if (e >= N_EDGES) return;
    int src, dst;
    if (g_is64) {
        src = ei32[2 * e];
        dst = ei32[2 * (N_EDGES + e)];
    } else {
        src = ei32[e];
        dst = ei32[N_EDGES + e];
    }
    if ((unsigned)src >= N_NODES || (unsigned)dst >= N_NODES) return;
    uint32_t bit = 1u << (dst & 31);
    uint32_t old = atomicOr(&g_mask[src * MASK_ROW_WORDS + (dst >> 5)], bit);
    if (!(old & bit)) {
        int pos = atomicAdd(&g_cnt[src], 1);
        if (pos < NBR_STRIDE)
            g_nbr[src * NBR_STRIDE + pos] = (uint16_t)dst;
    }
}

// ---------------------------------------------------------------------------
// Kernel C (stream 1): fp32 -> fp16 conversion for x AND W, float4-vectorized
// ---------------------------------------------------------------------------
__global__ void convert_kernel(const float* __restrict__ x, const float* __restrict__ W) {
    const int nx = N_NODES * (IN_F / 4);
    const int nw = OUT_F * (IN_F / 4);
    const float4* x4 = reinterpret_cast<const float4*>(x);
    const float4* w4 = reinterpret_cast<const float4*>(W);
    uint2* xdst = reinterpret_cast<uint2*>(g_xh);
    uint2* wdst = reinterpret_cast<uint2*>(g_wh);
    for (int i = blockIdx.x * blockDim.x + threadIdx.x; i < nx + nw;
         i += gridDim.x * blockDim.x) {
        float4 v = (i < nx) ? x4[i] : w4[i - nx];
        uint2 h;
        asm("cvt.rn.f16x2.f32 %0, %1, %2;" : "=r"(h.x) : "f"(v.y), "f"(v.x));
        asm("cvt.rn.f16x2.f32 %0, %1, %2;" : "=r"(h.y) : "f"(v.w), "f"(v.z));
        if (i < nx) xdst[i] = h; else wdst[i - nx] = h;
    }
}

// ---------------------------------------------------------------------------
// mma.sync fp16 GEMM:  hidden = fp16(x @ W^T + b)
// CTA 128x128, BK=32, 256 threads, 8 warps (2m x 4n), warp tile 64x32.
// 3-stage cp.async pipeline, ONE __syncthreads per K-chunk.
// ---------------------------------------------------------------------------
#define BM 128
#define BN 128
#define PAD_STRIDE 80
#define ST_A 0                 // A: 128 * 80 = 10240
#define ST_B 10240             // B: 128 * 80 = 10240
#define STAGE_SZ 20480
#define NSTAGE 3
#define GEMM_SMEM (NSTAGE * STAGE_SZ)   // 61440 dynamic

__device__ __forceinline__ void cp16(uint32_t s, const void* g) {
    asm volatile("cp.async.cg.shared.global [%0], [%1], 16;" :: "r"(s), "l"(g) : "memory");
}

#define LDM_X4(r, addr) \
    asm volatile("ldmatrix.sync.aligned.m8n8.x4.shared.b16 {%0,%1,%2,%3}, [%4];" \
        : "=r"((r)[0]), "=r"((r)[1]), "=r"((r)[2]), "=r"((r)[3]) : "r"(addr))

#define MMA16816(c, a, b0, b1) \
    asm volatile("mma.sync.aligned.m16n8k16.row.col.f32.f16.f16.f32 " \
        "{%0,%1,%2,%3}, {%4,%5,%6,%7}, {%8,%9}, {%0,%1,%2,%3};" \
        : "+f"((c)[0]), "+f"((c)[1]), "+f"((c)[2]), "+f"((c)[3]) \
        : "r"((a)[0]), "r"((a)[1]), "r"((a)[2]), "r"((a)[3]), "r"(b0), "r"(b1))

__global__ __launch_bounds__(256, 2) void gemm_tc_kernel(const float* __restrict__ bias)
{
    extern __shared__ char smem[];
    const uint32_t sbase = (uint32_t)__cvta_generic_to_shared(smem);
    const int tid  = threadIdx.x;
    const int wid  = tid >> 5;
    const int lane = tid & 31;
    const int bm = blockIdx.y * BM;
    const int bn = blockIdx.x * BN;

    const int warp_m = wid >> 2;            // 0..1, 64 rows
    const int warp_n = wid & 3;             // 0..3, 32 cols

    float acc[4][4][4];                     // [im][in(8col)][frag]
    #pragma unroll
    for (int i = 0; i < 4; i++)
        #pragma unroll
        for (int j = 0; j < 4; j++)
            #pragma unroll
            for (int k = 0; k < 4; k++) acc[i][j][k] = 0.f;

    // cp.async fill of one stage for K-chunk c (1024 x 16B, 4 per thread)
    auto issue = [&](int stage, int c) {
        uint32_t st = sbase + stage * STAGE_SZ;
        #pragma unroll
        for (int t = 0; t < 4; t++) {
            int i = tid + t * 256;
            if (i < 512) {                               // A tile (128 rows)
                int row = i >> 2, seg = i & 3;
                const uint32_t* gsrc = g_xh
                    + (size_t)(bm + row) * (IN_F / 2) + c * 16 + seg * 4;
                cp16(st + ST_A + row * PAD_STRIDE + seg * 16, gsrc);
            } else {                                     // B tile (128 rows)
                int j = i - 512;
                int row = j >> 2, seg = j & 3;
                const uint32_t* gsrc = g_wh
                    + (size_t)(bn + row) * (IN_F / 2) + c * 16 + seg * 4;
                cp16(st + ST_B + row * PAD_STRIDE + seg * 16, gsrc);
            }
        }
        asm volatile("cp.async.commit_group;" ::: "memory");
    };

    // ldmatrix per-thread source rows (proven addressing)
    const int a_row  = warp_m * 64 + (lane & 15);     // + im*16
    const int a_half = lane >> 4;
    const int b_row  = warp_n * 32 + ((lane & 16) >> 1) + (lane & 7);  // + g*16
    const int b_half = (lane >> 3) & 1;

    issue(0, 0);
    issue(1, 1);

    const int NCHUNK = IN_F / 32;   // 32
    for (int c = 0; c < NCHUNK; c++) {
        if (c + 1 < NCHUNK) {
            asm volatile("cp.async.wait_group 1;" ::: "memory");
        } else {
            asm volatile("cp.async.wait_group 0;" ::: "memory");
        }
        __syncthreads();
        if (c + 2 < NCHUNK) issue((c + 2) % NSTAGE, c + 2);

        const uint32_t st = sbase + (c % NSTAGE) * STAGE_SZ;
        #pragma unroll
        for (int ks = 0; ks < 2; ks++) {
            const int kb = ks * 32;                   // 16 fp16 = 32 bytes
            uint32_t ah[4][4];
            #pragma unroll
            for (int im = 0; im < 4; im++) {
                uint32_t addr = st + ST_A + (a_row + im * 16) * PAD_STRIDE + kb + a_half * 16;
                LDM_X4(ah[im], addr);
            }
            uint32_t bh[8];
            #pragma unroll
            for (int g = 0; g < 2; g++) {
                uint32_t addr = st + ST_B + (b_row + g * 16) * PAD_STRIDE + kb + b_half * 16;
                LDM_X4(bh + g * 4, addr);
            }
            #pragma unroll
            for (int im = 0; im < 4; im++) {
                #pragma unroll
                for (int in = 0; in < 4; in++) {
                    MMA16816(acc[im][in], ah[im], bh[in * 2], bh[in * 2 + 1]);
                }
            }
        }
    }

    // Epilogue: add bias, convert to half2, store packed fp16 hidden
    const int er = lane >> 2;
    const int ec = (lane & 3) * 2;
    #pragma unroll
    for (int im = 0; im < 4; im++) {
        int r0 = bm + warp_m * 64 + im * 16 + er;
        #pragma unroll
        for (int in = 0; in < 4; in++) {
            int col = bn + warp_n * 32 + in * 8 + ec;     // even
            float b0 = __ldg(&bias[col]);
            float b1 = __ldg(&bias[col + 1]);
            uint32_t h0, h1;
            asm("cvt.rn.f16x2.f32 %0, %1, %2;" : "=r"(h0)
                : "f"(acc[im][in][1] + b1), "f"(acc[im][in][0] + b0));
            asm("cvt.rn.f16x2.f32 %0, %1, %2;" : "=r"(h1)
                : "f"(acc[im][in][3] + b1), "f"(acc[im][in][2] + b0));
            g_hidden[(size_t)r0 * (OUT_F / 2) + (col >> 1)] = h0;
            g_hidden[(size_t)(r0 + 8) * (OUT_F / 2) + (col >> 1)] = h1;
        }
    }
}

// ---------------------------------------------------------------------------
// out[row] = relu( sum_{j in nbr[row]} hidden_fp16[j] )  fp32 accumulation.
// 1 block/row, 128 threads x (uint2 = 4 halves); 8 independent accumulators.
// ---------------------------------------------------------------------------
__global__ __launch_bounds__(128) void aggregate_kernel(float* __restrict__ out) {
    __shared__ uint16_t s_nbr[NBR_STRIDE];
    __shared__ int s_deg;

    const int row = blockIdx.x;
    const int t   = threadIdx.x;

    if (t == 0) s_deg = min(g_cnt[row], NBR_STRIDE);
    __syncthreads();
    const int deg = s_deg;
    for (int i = t; i < deg; i += 128)
        s_nbr[i] = g_nbr[row * NBR_STRIDE + i];
    __syncthreads();

    const uint2* H = reinterpret_cast<const uint2*>(g_hidden);

    float4 a[8];
    #pragma unroll
    for (int k = 0; k < 8; k++) a[k] = make_float4(0.f, 0.f, 0.f, 0.f);

    auto acc4 = [](float4& a, uint2 u) {
        float2 lo = __half22float2(*reinterpret_cast<__half2*>(&u.x));
        float2 hi = __half22float2(*reinterpret_cast<__half2*>(&u.y));
        a.x += lo.x; a.y += lo.y; a.z += hi.x; a.w += hi.y;
    };

    int i = 0;
    for (; i + 8 <= deg; i += 8) {
        uint2 u[8];
        #pragma unroll
        for (int k = 0; k < 8; k++) u[k] = H[s_nbr[i + k] * 128 + t];
        #pragma unroll
        for (int k = 0; k < 8; k++) acc4(a[k], u[k]);
    }
    for (; i < deg; i++) {
        uint2 u = H[s_nbr[i] * 128 + t];
        acc4(a[0], u);
    }

    #pragma unroll
    for (int k = 4; k > 0; k >>= 1)
        #pragma unroll
        for (int j = 0; j < k; j++) {
            a[j].x += a[j + k].x; a[j].y += a[j + k].y;
            a[j].z += a[j + k].z; a[j].w += a[j + k].w;
        }

    float4 r;
    r.x = fmaxf(a[0].x, 0.f);
    r.y = fmaxf(a[0].y, 0.f);
    r.z = fmaxf(a[0].z, 0.f);
    r.w = fmaxf(a[0].w, 0.f);
    reinterpret_cast<float4*>(out)[row * 128 + t] = r;
}

// ---------------------------------------------------------------------------
// Launch: fork-join — converts on s1 overlap mask prep on stream 0.
// ---------------------------------------------------------------------------
extern "C" void kernel_launch(void* const* d_in, const int* in_sizes, int n_in,
                              void* d_out, int out_size)
{
    const float* x    = (const float*)d_in[0];
    const float* W    = (const float*)d_in[1];
    const float* bias = (const float*)d_in[2];
    const int*   ei   = (const int*)d_in[3];
    float*       out  = (float*)d_out;

    (void)in_sizes; (void)n_in; (void)out_size;

    static cudaStream_t s1;
    static cudaEvent_t ev_fork, ev_conv;
    static bool init = false;
    if (!init) {
        cudaStreamCreateWithFlags(&s1, cudaStreamNonBlocking);
        cudaEventCreateWithFlags(&ev_fork, cudaEventDisableTiming);
        cudaEventCreateWithFlags(&ev_conv, cudaEventDisableTiming);
        cudaFuncSetAttribute(gemm_tc_kernel,
                             cudaFuncAttributeMaxDynamicSharedMemorySize, GEMM_SMEM);
        init = true;
    }

    // fork: converts run on s1 concurrently with mask prep on stream 0
    cudaEventRecord(ev_fork, 0);
    cudaStreamWaitEvent(s1, ev_fork, 0);
    convert_kernel<<<2048, 256, 0, s1>>>(x, W);
    cudaEventRecord(ev_conv, s1);

    prep_kernel<<<1024, 256>>>(ei);
    build_mask_kernel<<<N_EDGES / 256, 256>>>(ei);

    // join: GEMM needs converts done
    cudaStreamWaitEvent(0, ev_conv, 0);

    dim3 ggrid(OUT_F / BN, N_NODES / BM);   // (4, 64)
    gemm_tc_kernel<<<ggrid, 256, GEMM_SMEM>>>(bias);

    aggregate_kernel<<<N_NODES, 128>>>(out);
}

// round 12
// speedup vs baseline: 2.0893x; 1.0094x over previous
#include <cuda_runtime.h>
#include <cuda_fp16.h>
#include <cstdint>

// Problem constants (fixed shapes per reference)
#define N_NODES   8192
#define IN_F      1024
#define OUT_F     512
#define N_EDGES   262144
#define MASK_ROW_WORDS (N_NODES / 32)
#define MASK_WORDS     (N_NODES * MASK_ROW_WORDS)     // 8 MB
#define NBR_STRIDE 192

// Device-global scratch (allocation-free rule)
__device__ uint32_t g_mask[MASK_WORDS];
__device__ uint32_t g_hidden[N_NODES * (OUT_F / 2)];  // fp16 half2-packed, 8 MB
__device__ uint16_t g_nbr[N_NODES * NBR_STRIDE];
__device__ int      g_cnt[N_NODES];
__device__ int      g_is64;
// fp16 copies, packed half2 per u32 along K (k-contiguous)
__device__ uint32_t g_xh[N_NODES * (IN_F / 2)];       // 16 MB
__device__ uint32_t g_wh[OUT_F * (IN_F / 2)];         // 1 MB

// ---------------------------------------------------------------------------
// Kernel A (stream 0): zero mask + counters; block 0 also detects edge dtype.
// ---------------------------------------------------------------------------
__global__ void prep_kernel(const int* __restrict__ ei32) {
    int idx = blockIdx.x * blockDim.x + threadIdx.x;

    if (blockIdx.x == 0 && threadIdx.x < 32) {
        int lane = threadIdx.x;
        int nonzero = 0;
        #pragma unroll
        for (int i = 0; i < 3; i++) {
            if (ei32[2 * (lane + 32 * i) + 1] != 0) nonzero = 1;
        }
        unsigned any = __ballot_sync(0xFFFFFFFFu, nonzero);
        if (lane == 0) g_is64 = (any == 0u) ? 1 : 0;
    }

    uint4* p = reinterpret_cast<uint4*>(g_mask);
    int n4 = MASK_WORDS / 4;
    for (int i = idx; i < n4; i += gridDim.x * blockDim.x)
        p[i] = make_uint4(0u, 0u, 0u, 0u);
    if (idx < N_NODES) g_cnt[idx] = 0;
}

// ---------------------------------------------------------------------------
// Kernel B (stream 0): build deduped neighbor lists (set semantics via OR)
// ---------------------------------------------------------------------------
__global__ void build_mask_kernel(const int* __restrict__ ei32) {
    int e = blockIdx.x * blockDim.x + threadIdx.x;
    if (e >= N_EDGES) return;
    int src, dst;
    if (g_is64) {
        src = ei32[2 * e];
        dst = ei32[2 * (N_EDGES + e)];
    } else {
        src = ei32[e];
        dst = ei32[N_EDGES + e];
    }
    if ((unsigned)src >= N_NODES || (unsigned)dst >= N_NODES) return;
    uint32_t bit = 1u << (dst & 31);
    uint32_t old = atomicOr(&g_mask[src * MASK_ROW_WORDS + (dst >> 5)], bit);
    if (!(old & bit)) {
        int pos = atomicAdd(&g_cnt[src], 1);
        if (pos < NBR_STRIDE)
            g_nbr[src * NBR_STRIDE + pos] = (uint16_t)dst;
    }
}

// ---------------------------------------------------------------------------
// Kernel C (stream 1): fp32 -> fp16 conversion for x AND W, float4-vectorized
// ---------------------------------------------------------------------------
__global__ void convert_kernel(const float* __restrict__ x, const float* __restrict__ W) {
    const int nx = N_NODES * (IN_F / 4);
    const int nw = OUT_F * (IN_F / 4);
    const float4* x4 = reinterpret_cast<const float4*>(x);
    const float4* w4 = reinterpret_cast<const float4*>(W);
    uint2* xdst = reinterpret_cast<uint2*>(g_xh);
    uint2* wdst = reinterpret_cast<uint2*>(g_wh);
    for (int i = blockIdx.x * blockDim.x + threadIdx.x; i < nx + nw;
         i += gridDim.x * blockDim.x) {
        float4 v = (i < nx) ? x4[i] : w4[i - nx];
        uint2 h;
        asm("cvt.rn.f16x2.f32 %0, %1, %2;" : "=r"(h.x) : "f"(v.y), "f"(v.x));
        asm("cvt.rn.f16x2.f32 %0, %1, %2;" : "=r"(h.y) : "f"(v.w), "f"(v.z));
        if (i < nx) xdst[i] = h; else wdst[i - nx] = h;
    }
}

// ---------------------------------------------------------------------------
// mma.sync fp16 GEMM half:  hidden[:, bn_base:bn_base+256] = fp16(x @ W^T + b)
// CTA 128x128, BK=32, 256 threads, 8 warps (2m x 4n), warp tile 64x32.
// 3-stage cp.async pipeline, ONE __syncthreads per K-chunk. grid (2,64).
// ---------------------------------------------------------------------------
#define BM 128
#define BN 128
#define PAD_STRIDE 80
#define ST_A 0                 // A: 128 * 80 = 10240
#define ST_B 10240             // B: 128 * 80 = 10240
#define STAGE_SZ 20480
#define NSTAGE 3
#define GEMM_SMEM (NSTAGE * STAGE_SZ)   // 61440 dynamic

__device__ __forceinline__ void cp16(uint32_t s, const void* g) {
    asm volatile("cp.async.cg.shared.global [%0], [%1], 16;" :: "r"(s), "l"(g) : "memory");
}

#define LDM_X4(r, addr) \
    asm volatile("ldmatrix.sync.aligned.m8n8.x4.shared.b16 {%0,%1,%2,%3}, [%4];" \
        : "=r"((r)[0]), "=r"((r)[1]), "=r"((r)[2]), "=r"((r)[3]) : "r"(addr))

#define MMA16816(c, a, b0, b1) \
    asm volatile("mma.sync.aligned.m16n8k16.row.col.f32.f16.f16.f32 " \
        "{%0,%1,%2,%3}, {%4,%5,%6,%7}, {%8,%9}, {%0,%1,%2,%3};" \
        : "+f"((c)[0]), "+f"((c)[1]), "+f"((c)[2]), "+f"((c)[3]) \
        : "r"((a)[0]), "r"((a)[1]), "r"((a)[2]), "r"((a)[3]), "r"(b0), "r"(b1))

__global__ __launch_bounds__(256, 2) void gemm_tc_kernel(const float* __restrict__ bias,
                                                          int bn_base)
{
    extern __shared__ char smem[];
    const uint32_t sbase = (uint32_t)__cvta_generic_to_shared(smem);
    const int tid  = threadIdx.x;
    const int wid  = tid >> 5;
    const int lane = tid & 31;
    const int bm = blockIdx.y * BM;
    const int bn = bn_base + blockIdx.x * BN;

    const int warp_m = wid >> 2;            // 0..1, 64 rows
    const int warp_n = wid & 3;             // 0..3, 32 cols

    float acc[4][4][4];
    #pragma unroll
    for (int i = 0; i < 4; i++)
        #pragma unroll
        for (int j = 0; j < 4; j++)
            #pragma unroll
            for (int k = 0; k < 4; k++) acc[i][j][k] = 0.f;

    auto issue = [&](int stage, int c) {
        uint32_t st = sbase + stage * STAGE_SZ;
        #pragma unroll
        for (int t = 0; t < 4; t++) {
            int i = tid + t * 256;
            if (i < 512) {                               // A tile (128 rows)
                int row = i >> 2, seg = i & 3;
                const uint32_t* gsrc = g_xh
                    + (size_t)(bm + row) * (IN_F / 2) + c * 16 + seg * 4;
                cp16(st + ST_A + row * PAD_STRIDE + seg * 16, gsrc);
            } else {                                     // B tile (128 rows)
                int j = i - 512;
                int row = j >> 2, seg = j & 3;
                const uint32_t* gsrc = g_wh
                    + (size_t)(bn + row) * (IN_F / 2) + c * 16 + seg * 4;
                cp16(st + ST_B + row * PAD_STRIDE + seg * 16, gsrc);
            }
        }
        asm volatile("cp.async.commit_group;" ::: "memory");
    };

    const int a_row  = warp_m * 64 + (lane & 15);
    const int a_half = lane >> 4;
    const int b_row  = warp_n * 32 + ((lane & 16) >> 1) + (lane & 7);
    const int b_half = (lane >> 3) & 1;

    issue(0, 0);
    issue(1, 1);

    const int NCHUNK = IN_F / 32;   // 32
    for (int c = 0; c < NCHUNK; c++) {
        if (c + 1 < NCHUNK) {
            asm volatile("cp.async.wait_group 1;" ::: "memory");
        } else {
            asm volatile("cp.async.wait_group 0;" ::: "memory");
        }
        __syncthreads();
        if (c + 2 < NCHUNK) issue((c + 2) % NSTAGE, c + 2);

        const uint32_t st = sbase + (c % NSTAGE) * STAGE_SZ;
        #pragma unroll
        for (int ks = 0; ks < 2; ks++) {
            const int kb = ks * 32;
            uint32_t ah[4][4];
            #pragma unroll
            for (int im = 0; im < 4; im++) {
                uint32_t addr = st + ST_A + (a_row + im * 16) * PAD_STRIDE + kb + a_half * 16;
                LDM_X4(ah[im], addr);
            }
            uint32_t bh[8];
            #pragma unroll
            for (int g = 0; g < 2; g++) {
                uint32_t addr = st + ST_B + (b_row + g * 16) * PAD_STRIDE + kb + b_half * 16;
                LDM_X4(bh + g * 4, addr);
            }
            #pragma unroll
            for (int im = 0; im < 4; im++) {
                #pragma unroll
                for (int in = 0; in < 4; in++) {
                    MMA16816(acc[im][in], ah[im], bh[in * 2], bh[in * 2 + 1]);
                }
            }
        }
    }

    // Epilogue: add bias, convert to half2, store packed fp16 hidden
    const int er = lane >> 2;
    const int ec = (lane & 3) * 2;
    #pragma unroll
    for (int im = 0; im < 4; im++) {
        int r0 = bm + warp_m * 64 + im * 16 + er;
        #pragma unroll
        for (int in = 0; in < 4; in++) {
            int col = bn + warp_n * 32 + in * 8 + ec;
            float b0 = __ldg(&bias[col]);
            float b1 = __ldg(&bias[col + 1]);
            uint32_t h0, h1;
            asm("cvt.rn.f16x2.f32 %0, %1, %2;" : "=r"(h0)
                : "f"(acc[im][in][1] + b1), "f"(acc[im][in][0] + b0));
            asm("cvt.rn.f16x2.f32 %0, %1, %2;" : "=r"(h1)
                : "f"(acc[im][in][3] + b1), "f"(acc[im][in][2] + b0));
            g_hidden[(size_t)r0 * (OUT_F / 2) + (col >> 1)] = h0;
            g_hidden[(size_t)(r0 + 8) * (OUT_F / 2) + (col >> 1)] = h1;
        }
    }
}

// ---------------------------------------------------------------------------
// Aggregate HALF (feature cols [base*4, base*4+256)):
// out[row, half] = relu( sum_{j in nbr[row]} hidden_fp16[j, half] )
// 64 threads/block, each thread one uint2 (4 features); 8 accumulators.
// ---------------------------------------------------------------------------
__global__ __launch_bounds__(64) void aggregate_half_kernel(float* __restrict__ out,
                                                            int base)
{
    __shared__ uint16_t s_nbr[NBR_STRIDE];
    __shared__ int s_deg;

    const int row = blockIdx.x;
    const int t   = threadIdx.x;              // 0..63
    const int col = base + t;                 // uint2 column 0..127

    if (t == 0) s_deg = min(g_cnt[row], NBR_STRIDE);
    __syncthreads();
    const int deg = s_deg;
    for (int i = t; i < deg; i += 64)
        s_nbr[i] = g_nbr[row * NBR_STRIDE + i];
    __syncthreads();

    const uint2* H = reinterpret_cast<const uint2*>(g_hidden);

    float4 a[8];
    #pragma unroll
    for (int k = 0; k < 8; k++) a[k] = make_float4(0.f, 0.f, 0.f, 0.f);

    auto acc4 = [](float4& a, uint2 u) {
        float2 lo = __half22float2(*reinterpret_cast<__half2*>(&u.x));
        float2 hi = __half22float2(*reinterpret_cast<__half2*>(&u.y));
        a.x += lo.x; a.y += lo.y; a.z += hi.x; a.w += hi.y;
    };

    int i = 0;
    for (; i + 8 <= deg; i += 8) {
        uint2 u[8];
        #pragma unroll
        for (int k = 0; k < 8; k++) u[k] = H[s_nbr[i + k] * 128 + col];
        #pragma unroll
        for (int k = 0; k < 8; k++) acc4(a[k], u[k]);
    }
    for (; i < deg; i++) {
        uint2 u = H[s_nbr[i] * 128 + col];
        acc4(a[0], u);
    }

    #pragma unroll
    for (int k = 4; k > 0; k >>= 1)
        #pragma unroll
        for (int j = 0; j < k; j++) {
            a[j].x += a[j + k].x; a[j].y += a[j + k].y;
            a[j].z += a[j + k].z; a[j].w += a[j + k].w;
        }

    float4 r;
    r.x = fmaxf(a[0].x, 0.f);
    r.y = fmaxf(a[0].y, 0.f);
    r.z = fmaxf(a[0].z, 0.f);
    r.w = fmaxf(a[0].w, 0.f);
    reinterpret_cast<float4*>(out)[row * 128 + col] = r;
}

// ---------------------------------------------------------------------------
// Launch topology (events become graph edges under capture):
//   s0: prep -> build -> [ev_build] -> (wait ev_conv) gemmA(bn 0) -> agg0 -> (wait ev_d1)
//   s1: (wait ev_fork) convert -> [ev_conv] -> gemmB(bn 256) -> (wait ev_build) agg1 -> [ev_d1]
// gemmA/gemmB run concurrently (tensor-bound); agg halves overlap GEMM tails
// and each other (L2-bound) — disjoint resources.
// ---------------------------------------------------------------------------
extern "C" void kernel_launch(void* const* d_in, const int* in_sizes, int n_in,
                              void* d_out, int out_size)
{
    const float* x    = (const float*)d_in[0];
    const float* W    = (const float*)d_in[1];
    const float* bias = (const float*)d_in[2];
    const int*   ei   = (const int*)d_in[3];
    float*       out  = (float*)d_out;

    (void)in_sizes; (void)n_in; (void)out_size;

    static cudaStream_t s1;
    static cudaEvent_t ev_fork, ev_conv, ev_build, ev_d1;
    static bool init = false;
    if (!init) {
        cudaStreamCreateWithFlags(&s1, cudaStreamNonBlocking);
        cudaEventCreateWithFlags(&ev_fork, cudaEventDisableTiming);
        cudaEventCreateWithFlags(&ev_conv, cudaEventDisableTiming);
        cudaEventCreateWithFlags(&ev_build, cudaEventDisableTiming);
        cudaEventCreateWithFlags(&ev_d1, cudaEventDisableTiming);
        cudaFuncSetAttribute(gemm_tc_kernel,
                             cudaFuncAttributeMaxDynamicSharedMemorySize, GEMM_SMEM);
        init = true;
    }

    dim3 ggrid(2, N_NODES / BM);            // half-N GEMM: (2, 64)

    // fork
    cudaEventRecord(ev_fork, 0);
    cudaStreamWaitEvent(s1, ev_fork, 0);

    // s1: convert -> gemmB -> agg1
    convert_kernel<<<2048, 256, 0, s1>>>(x, W);
    cudaEventRecord(ev_conv, s1);
    gemm_tc_kernel<<<ggrid, 256, GEMM_SMEM, s1>>>(bias, 256);

    // s0: prep -> build -> gemmA -> agg0
    prep_kernel<<<1024, 256>>>(ei);
    build_mask_kernel<<<N_EDGES / 256, 256>>>(ei);
    cudaEventRecord(ev_build, 0);
    cudaStreamWaitEvent(0, ev_conv, 0);
    gemm_tc_kernel<<<ggrid, 256, GEMM_SMEM>>>(bias, 0);
    aggregate_half_kernel<<<N_NODES, 64>>>(out, 0);

    // s1: agg1 after its gemm half + build
    cudaStreamWaitEvent(s1, ev_build, 0);
    aggregate_half_kernel<<<N_NODES, 64, 0, s1>>>(out, 64);
    cudaEventRecord(ev_d1, s1);

    // join
    cudaStreamWaitEvent(0, ev_d1, 0);
}

// round 13
// speedup vs baseline: 2.2342x; 1.0694x over previous
#include <cuda_runtime.h>
#include <cuda_fp16.h>
#include <cstdint>

// Problem constants (fixed shapes per reference)
#define N_NODES   8192
#define IN_F      1024
#define OUT_F     512
#define N_EDGES   262144
#define NBR_STRIDE 192

// Device-global scratch (allocation-free rule)
__device__ uint32_t g_hidden[N_NODES * (OUT_F / 2)];  // fp16 half2-packed, 8 MB
__device__ uint16_t g_nbr[N_NODES * NBR_STRIDE];      // edge lists WITH duplicates
__device__ int      g_cnt[N_NODES];
__device__ int      g_is64;
// fp16 copies, packed half2 per u32 along K (k-contiguous)
__device__ uint32_t g_xh[N_NODES * (IN_F / 2)];       // 16 MB
__device__ uint32_t g_wh[OUT_F * (IN_F / 2)];         // 1 MB

// ---------------------------------------------------------------------------
// Kernel A (stream 0): zero per-row counters; block 0 detects edge dtype.
// ---------------------------------------------------------------------------
__global__ void prep_kernel(const int* __restrict__ ei32) {
    int idx = blockIdx.x * blockDim.x + threadIdx.x;
    if (blockIdx.x == 0 && threadIdx.x < 32) {
        int lane = threadIdx.x;
        int nonzero = 0;
        #pragma unroll
        for (int i = 0; i < 3; i++) {
            if (ei32[2 * (lane + 32 * i) + 1] != 0) nonzero = 1;
        }
        unsigned any = __ballot_sync(0xFFFFFFFFu, nonzero);
        if (lane == 0) g_is64 = (any == 0u) ? 1 : 0;
    }
    if (idx < N_NODES) g_cnt[idx] = 0;
}

// ---------------------------------------------------------------------------
// Kernel B (stream 0): append ALL edges (dups kept; dedup happens in agg).
// Single atomicAdd per edge — no atomicOr round-trip, no 8MB mask.
// ---------------------------------------------------------------------------
__global__ void build_kernel(const int* __restrict__ ei32) {
    int e = blockIdx.x * blockDim.x + threadIdx.x;
    if (e >= N_EDGES) return;
    int src, dst;
    if (g_is64) {
        src = ei32[2 * e];
        dst = ei32[2 * (N_EDGES + e)];
    } else {
        src = ei32[e];
        dst = ei32[N_EDGES + e];
    }
    if ((unsigned)src >= N_NODES || (unsigned)dst >= N_NODES) return;
    int pos = atomicAdd(&g_cnt[src], 1);
    if (pos < NBR_STRIDE)
        g_nbr[src * NBR_STRIDE + pos] = (uint16_t)dst;
}

// ---------------------------------------------------------------------------
// Kernel C (stream 1): fp32 -> fp16 conversion for x AND W, float4-vectorized
// ---------------------------------------------------------------------------
__global__ void convert_kernel(const float* __restrict__ x, const float* __restrict__ W) {
    const int nx = N_NODES * (IN_F / 4);
    const int nw = OUT_F * (IN_F / 4);
    const float4* x4 = reinterpret_cast<const float4*>(x);
    const float4* w4 = reinterpret_cast<const float4*>(W);
    uint2* xdst = reinterpret_cast<uint2*>(g_xh);
    uint2* wdst = reinterpret_cast<uint2*>(g_wh);
    for (int i = blockIdx.x * blockDim.x + threadIdx.x; i < nx + nw;
         i += gridDim.x * blockDim.x) {
        float4 v = (i < nx) ? x4[i] : w4[i - nx];
        uint2 h;
        asm("cvt.rn.f16x2.f32 %0, %1, %2;" : "=r"(h.x) : "f"(v.y), "f"(v.x));
        asm("cvt.rn.f16x2.f32 %0, %1, %2;" : "=r"(h.y) : "f"(v.w), "f"(v.z));
        if (i < nx) xdst[i] = h; else wdst[i - nx] = h;
    }
}

// ---------------------------------------------------------------------------
// mma.sync fp16 GEMM half (cols [bn_base, bn_base+256)):
// CTA 128x128, BK=64 (two proven 32-k sub-tiles per stage), 2-stage,
// ONE __syncthreads per 64-k chunk, 16 chunks. 8 warps (2m x 4n), tile 64x32.
// ---------------------------------------------------------------------------
#define BM 128
#define BN 128
#define PAD_STRIDE 80
#define SUB_SZ 20480           // one 32-k sub-stage: A(10240) + B(10240)
#define STAGE_SZ 40960         // two sub-chunks
#define GEMM_SMEM (2 * STAGE_SZ)   // 81920 dynamic, occ 2

__device__ __forceinline__ void cp16(uint32_t s, const void* g) {
    asm volatile("cp.async.cg.shared.global [%0], [%1], 16;" :: "r"(s), "l"(g) : "memory");
}

#define LDM_X4(r, addr) \
    asm volatile("ldmatrix.sync.aligned.m8n8.x4.shared.b16 {%0,%1,%2,%3}, [%4];" \
        : "=r"((r)[0]), "=r"((r)[1]), "=r"((r)[2]), "=r"((r)[3]) : "r"(addr))

#define MMA16816(c, a, b0, b1) \
    asm volatile("mma.sync.aligned.m16n8k16.row.col.f32.f16.f16.f32 " \
        "{%0,%1,%2,%3}, {%4,%5,%6,%7}, {%8,%9}, {%0,%1,%2,%3};" \
        : "+f"((c)[0]), "+f"((c)[1]), "+f"((c)[2]), "+f"((c)[3]) \
        : "r"((a)[0]), "r"((a)[1]), "r"((a)[2]), "r"((a)[3]), "r"(b0), "r"(b1))

__global__ __launch_bounds__(256, 2) void gemm_tc_kernel(const float* __restrict__ bias,
                                                          int bn_base)
{
    extern __shared__ char smem[];
    const uint32_t sbase = (uint32_t)__cvta_generic_to_shared(smem);
    const int tid  = threadIdx.x;
    const int wid  = tid >> 5;
    const int lane = tid & 31;
    const int bm = blockIdx.y * BM;
    const int bn = bn_base + blockIdx.x * BN;

    const int warp_m = wid >> 2;            // 0..1, 64 rows
    const int warp_n = wid & 3;             // 0..3, 32 cols

    float acc[4][4][4];
    #pragma unroll
    for (int i = 0; i < 4; i++)
        #pragma unroll
        for (int j = 0; j < 4; j++)
            #pragma unroll
            for (int k = 0; k < 4; k++) acc[i][j][k] = 0.f;

    // cp.async fill of one 64-k stage (2048 x 16B = 8 per thread)
    // i in [0,512): A sub0; [512,1024): B sub0; [1024,1536): A sub1; [1536,2048): B sub1
    auto issue = [&](int stage, int c) {
        uint32_t st = sbase + stage * STAGE_SZ;
        #pragma unroll
        for (int t = 0; t < 8; t++) {
            int i = tid + t * 256;
            int sub = (i >> 10) & 1;              // 0 or 1
            int isB = (i >> 9) & 1;               // A or B within sub
            int idx = i & 511;
            int row = idx >> 2, seg = idx & 3;
            const uint32_t* gbase = isB ? g_wh : g_xh;
            int grow = (isB ? bn : bm) + row;
            const uint32_t* gsrc = gbase
                + (size_t)grow * (IN_F / 2) + c * 32 + sub * 16 + seg * 4;
            cp16(st + sub * SUB_SZ + isB * 10240 + row * PAD_STRIDE + seg * 16, gsrc);
        }
        asm volatile("cp.async.commit_group;" ::: "memory");
    };

    const int a_row  = warp_m * 64 + (lane & 15);
    const int a_half = lane >> 4;
    const int b_row  = warp_n * 32 + ((lane & 16) >> 1) + (lane & 7);
    const int b_half = (lane >> 3) & 1;

    issue(0, 0);

    const int NCHUNK = IN_F / 64;   // 16
    for (int c = 0; c < NCHUNK; c++) {
        asm volatile("cp.async.wait_group 0;" ::: "memory");
        __syncthreads();
        if (c + 1 < NCHUNK) issue((c + 1) & 1, c + 1);

        const uint32_t st = sbase + (c & 1) * STAGE_SZ;
        #pragma unroll
        for (int ks = 0; ks < 4; ks++) {
            const uint32_t sb2 = st + (ks >> 1) * SUB_SZ;
            const int kb = (ks & 1) * 32;
            uint32_t ah[4][4];
            #pragma unroll
            for (int im = 0; im < 4; im++) {
                uint32_t addr = sb2 + (a_row + im * 16) * PAD_STRIDE + kb + a_half * 16;
                LDM_X4(ah[im], addr);
            }
            uint32_t bh[8];
            #pragma unroll
            for (int g = 0; g < 2; g++) {
                uint32_t addr = sb2 + 10240 + (b_row + g * 16) * PAD_STRIDE + kb + b_half * 16;
                LDM_X4(bh + g * 4, addr);
            }
            #pragma unroll
            for (int im = 0; im < 4; im++) {
                #pragma unroll
                for (int in = 0; in < 4; in++) {
                    MMA16816(acc[im][in], ah[im], bh[in * 2], bh[in * 2 + 1]);
                }
            }
        }
    }

    // Epilogue: add bias, convert to half2, store packed fp16 hidden
    const int er = lane >> 2;
    const int ec = (lane & 3) * 2;
    #pragma unroll
    for (int im = 0; im < 4; im++) {
        int r0 = bm + warp_m * 64 + im * 16 + er;
        #pragma unroll
        for (int in = 0; in < 4; in++) {
            int col = bn + warp_n * 32 + in * 8 + ec;
            float b0 = __ldg(&bias[col]);
            float b1 = __ldg(&bias[col + 1]);
            uint32_t h0, h1;
            asm("cvt.rn.f16x2.f32 %0, %1, %2;" : "=r"(h0)
                : "f"(acc[im][in][1] + b1), "f"(acc[im][in][0] + b0));
            asm("cvt.rn.f16x2.f32 %0, %1, %2;" : "=r"(h1)
                : "f"(acc[im][in][3] + b1), "f"(acc[im][in][2] + b0));
            g_hidden[(size_t)r0 * (OUT_F / 2) + (col >> 1)] = h0;
            g_hidden[(size_t)(r0 + 8) * (OUT_F / 2) + (col >> 1)] = h1;
        }
    }
}

// ---------------------------------------------------------------------------
// Aggregate HALF (uint2 cols [base, base+64)):
// dedup duplicates via 1KB smem bitmask, then gather + relu.
// ---------------------------------------------------------------------------
__global__ __launch_bounds__(64) void aggregate_half_kernel(float* __restrict__ out,
                                                            int base)
{
    __shared__ uint32_t s_mask[N_NODES / 32];   // 1 KB
    __shared__ uint16_t s_list[NBR_STRIDE];
    __shared__ int s_n;

    const int row = blockIdx.x;
    const int t   = threadIdx.x;              // 0..63
    const int col = base + t;                 // uint2 column 0..127

    #pragma unroll
    for (int i = 0; i < (N_NODES / 32) / 64; i++)
        s_mask[t + i * 64] = 0u;
    if (t == 0) s_n = 0;
    __syncthreads();

    const int deg_raw = min(g_cnt[row], NBR_STRIDE);
    for (int i = t; i < deg_raw; i += 64) {
        int j = g_nbr[row * NBR_STRIDE + i];
        uint32_t bit = 1u << (j & 31);
        uint32_t old = atomicOr(&s_mask[j >> 5], bit);
        if (!(old & bit)) {
            int p = atomicAdd(&s_n, 1);
            s_list[p] = (uint16_t)j;
        }
    }
    __syncthreads();
    const int deg = s_n;

    const uint2* H = reinterpret_cast<const uint2*>(g_hidden);

    float4 a[8];
    #pragma unroll
    for (int k = 0; k < 8; k++) a[k] = make_float4(0.f, 0.f, 0.f, 0.f);

    auto acc4 = [](float4& a, uint2 u) {
        float2 lo = __half22float2(*reinterpret_cast<__half2*>(&u.x));
        float2 hi = __half22float2(*reinterpret_cast<__half2*>(&u.y));
        a.x += lo.x; a.y += lo.y; a.z += hi.x; a.w += hi.y;
    };

    int i = 0;
    for (; i + 8 <= deg; i += 8) {
        uint2 u[8];
        #pragma unroll
        for (int k = 0; k < 8; k++) u[k] = H[s_list[i + k] * 128 + col];
        #pragma unroll
        for (int k = 0; k < 8; k++) acc4(a[k], u[k]);
    }
    for (; i < deg; i++) {
        uint2 u = H[s_list[i] * 128 + col];
        acc4(a[0], u);
    }

    #pragma unroll
    for (int k = 4; k > 0; k >>= 1)
        #pragma unroll
        for (int j = 0; j < k; j++) {
            a[j].x += a[j + k].x; a[j].y += a[j + k].y;
            a[j].z += a[j + k].z; a[j].w += a[j + k].w;
        }

    float4 r;
    r.x = fmaxf(a[0].x, 0.f);
    r.y = fmaxf(a[0].y, 0.f);
    r.z = fmaxf(a[0].z, 0.f);
    r.w = fmaxf(a[0].w, 0.f);
    reinterpret_cast<float4*>(out)[row * 128 + col] = r;
}

// ---------------------------------------------------------------------------
// Launch topology (proven R12 event graph):
//   s0: prep -> build -> [ev_build] -> (wait ev_conv) gemmA(0) -> agg0 -> (wait ev_d1)
//   s1: (wait ev_fork) convert -> [ev_conv] -> gemmB(256) -> (wait ev_build) agg1 -> [ev_d1]
// ---------------------------------------------------------------------------
extern "C" void kernel_launch(void* const* d_in, const int* in_sizes, int n_in,
                              void* d_out, int out_size)
{
    const float* x    = (const float*)d_in[0];
    const float* W    = (const float*)d_in[1];
    const float* bias = (const float*)d_in[2];
    const int*   ei   = (const int*)d_in[3];
    float*       out  = (float*)d_out;

    (void)in_sizes; (void)n_in; (void)out_size;

    static cudaStream_t s1;
    static cudaEvent_t ev_fork, ev_conv, ev_build, ev_d1;
    static bool init = false;
    if (!init) {
        cudaStreamCreateWithFlags(&s1, cudaStreamNonBlocking);
        cudaEventCreateWithFlags(&ev_fork, cudaEventDisableTiming);
        cudaEventCreateWithFlags(&ev_conv, cudaEventDisableTiming);
        cudaEventCreateWithFlags(&ev_build, cudaEventDisableTiming);
        cudaEventCreateWithFlags(&ev_d1, cudaEventDisableTiming);
        cudaFuncSetAttribute(gemm_tc_kernel,
                             cudaFuncAttributeMaxDynamicSharedMemorySize, GEMM_SMEM);
        init = true;
    }

    dim3 ggrid(2, N_NODES / BM);            // half-N GEMM: (2, 64)

    // fork
    cudaEventRecord(ev_fork, 0);
    cudaStreamWaitEvent(s1, ev_fork, 0);

    // s1: convert -> gemmB -> agg1
    convert_kernel<<<2048, 256, 0, s1>>>(x, W);
    cudaEventRecord(ev_conv, s1);
    gemm_tc_kernel<<<ggrid, 256, GEMM_SMEM, s1>>>(bias, 256);

    // s0: prep -> build -> gemmA -> agg0
    prep_kernel<<<32, 256>>>(ei);
    build_kernel<<<N_EDGES / 256, 256>>>(ei);
    cudaEventRecord(ev_build, 0);
    cudaStreamWaitEvent(0, ev_conv, 0);
    gemm_tc_kernel<<<ggrid, 256, GEMM_SMEM>>>(bias, 0);
    aggregate_half_kernel<<<N_NODES, 64>>>(out, 0);

    // s1: agg1 after its gemm half + build
    cudaStreamWaitEvent(s1, ev_build, 0);
    aggregate_half_kernel<<<N_NODES, 64, 0, s1>>>(out, 64);
    cudaEventRecord(ev_d1, s1);

    // join
    cudaStreamWaitEvent(0, ev_d1, 0);
}

// round 14
// speedup vs baseline: 2.3313x; 1.0434x over previous
#include <cuda_runtime.h>
#include <cuda_fp16.h>
#include <cstdint>

// Problem constants (fixed shapes per reference)
#define N_NODES   8192
#define IN_F      1024
#define OUT_F     512
#define N_EDGES   262144
#define NBR_STRIDE 192

// Device-global scratch (allocation-free rule)
__device__ uint32_t g_hidden[N_NODES * (OUT_F / 2)];  // fp16 half2-packed, 8 MB
__device__ uint16_t g_nbr[N_NODES * NBR_STRIDE];      // edge lists WITH duplicates
__device__ int      g_cnt[N_NODES];
__device__ int      g_is64;
// fp16 copies, packed half2 per u32 along K (k-contiguous)
__device__ uint32_t g_xh[N_NODES * (IN_F / 2)];       // 16 MB
__device__ uint32_t g_wh[OUT_F * (IN_F / 2)];         // 1 MB

// ---------------------------------------------------------------------------
// Kernel A (s2): zero per-row counters; block 0 detects edge dtype.
// ---------------------------------------------------------------------------
__global__ void prep_kernel(const int* __restrict__ ei32) {
    int idx = blockIdx.x * blockDim.x + threadIdx.x;
    if (blockIdx.x == 0 && threadIdx.x < 32) {
        int lane = threadIdx.x;
        int nonzero = 0;
        #pragma unroll
        for (int i = 0; i < 3; i++) {
            if (ei32[2 * (lane + 32 * i) + 1] != 0) nonzero = 1;
        }
        unsigned any = __ballot_sync(0xFFFFFFFFu, nonzero);
        if (lane == 0) g_is64 = (any == 0u) ? 1 : 0;
    }
    if (idx < N_NODES) g_cnt[idx] = 0;
}

// ---------------------------------------------------------------------------
// Kernel B (s2): append ALL edges, 2 edges/thread (wide loads, ILP 2).
// ---------------------------------------------------------------------------
__global__ void build_kernel(const int* __restrict__ ei32) {
    int p = blockIdx.x * blockDim.x + threadIdx.x;   // pair index
    if (p >= N_EDGES / 2) return;
    int s0, s1, d0, d1;
    if (g_is64) {
        int4 sv = *reinterpret_cast<const int4*>(ei32 + 4 * p);
        int4 dv = *reinterpret_cast<const int4*>(ei32 + 2 * N_EDGES + 4 * p);
        s0 = sv.x; s1 = sv.z;
        d0 = dv.x; d1 = dv.z;
    } else {
        int2 sv = *reinterpret_cast<const int2*>(ei32 + 2 * p);
        int2 dv = *reinterpret_cast<const int2*>(ei32 + N_EDGES + 2 * p);
        s0 = sv.x; s1 = sv.y;
        d0 = dv.x; d1 = dv.y;
    }
    if ((unsigned)s0 < N_NODES && (unsigned)d0 < N_NODES) {
        int pos = atomicAdd(&g_cnt[s0], 1);
        if (pos < NBR_STRIDE) g_nbr[s0 * NBR_STRIDE + pos] = (uint16_t)d0;
    }
    if ((unsigned)s1 < N_NODES && (unsigned)d1 < N_NODES) {
        int pos = atomicAdd(&g_cnt[s1], 1);
        if (pos < NBR_STRIDE) g_nbr[s1 * NBR_STRIDE + pos] = (uint16_t)d1;
    }
}

// ---------------------------------------------------------------------------
// Kernel C (s1): fp32 -> fp16 for x AND W, ILP 2 (two float4 per iteration)
// ---------------------------------------------------------------------------
__global__ void convert_kernel(const float* __restrict__ x, const float* __restrict__ W) {
    const int nx = N_NODES * (IN_F / 4);
    const int nw = OUT_F * (IN_F / 4);
    const int ntot = nx + nw;
    const float4* x4 = reinterpret_cast<const float4*>(x);
    const float4* w4 = reinterpret_cast<const float4*>(W);
    uint2* xdst = reinterpret_cast<uint2*>(g_xh);
    uint2* wdst = reinterpret_cast<uint2*>(g_wh);
    const int stride = gridDim.x * blockDim.x;
    for (int i = blockIdx.x * blockDim.x + threadIdx.x; i < ntot; i += 2 * stride) {
        int j = i + stride;
        float4 v0 = (i < nx) ? x4[i] : w4[i - nx];
        float4 v1 = (j < ntot) ? ((j < nx) ? x4[j] : w4[j - nx])
                               : make_float4(0.f, 0.f, 0.f, 0.f);
        uint2 h0, h1;
        asm("cvt.rn.f16x2.f32 %0, %1, %2;" : "=r"(h0.x) : "f"(v0.y), "f"(v0.x));
        asm("cvt.rn.f16x2.f32 %0, %1, %2;" : "=r"(h0.y) : "f"(v0.w), "f"(v0.z));
        asm("cvt.rn.f16x2.f32 %0, %1, %2;" : "=r"(h1.x) : "f"(v1.y), "f"(v1.x));
        asm("cvt.rn.f16x2.f32 %0, %1, %2;" : "=r"(h1.y) : "f"(v1.w), "f"(v1.z));
        if (i < nx) xdst[i] = h0; else wdst[i - nx] = h0;
        if (j < ntot) { if (j < nx) xdst[j] = h1; else wdst[j - nx] = h1; }
    }
}

// ---------------------------------------------------------------------------
// mma.sync fp16 GEMM half (cols [bn_base, bn_base+256)):
// CTA 128x128, BK=64 (two 32-k sub-tiles), 2-stage, ONE sync per chunk.
// ---------------------------------------------------------------------------
#define BM 128
#define BN 128
#define PAD_STRIDE 80
#define SUB_SZ 20480
#define STAGE_SZ 40960
#define GEMM_SMEM (2 * STAGE_SZ)   // 81920 dynamic, occ 2

__device__ __forceinline__ void cp16(uint32_t s, const void* g) {
    asm volatile("cp.async.cg.shared.global [%0], [%1], 16;" :: "r"(s), "l"(g) : "memory");
}

#define LDM_X4(r, addr) \
    asm volatile("ldmatrix.sync.aligned.m8n8.x4.shared.b16 {%0,%1,%2,%3}, [%4];" \
        : "=r"((r)[0]), "=r"((r)[1]), "=r"((r)[2]), "=r"((r)[3]) : "r"(addr))

#define MMA16816(c, a, b0, b1) \
    asm volatile("mma.sync.aligned.m16n8k16.row.col.f32.f16.f16.f32 " \
        "{%0,%1,%2,%3}, {%4,%5,%6,%7}, {%8,%9}, {%0,%1,%2,%3};" \
        : "+f"((c)[0]), "+f"((c)[1]), "+f"((c)[2]), "+f"((c)[3]) \
        : "r"((a)[0]), "r"((a)[1]), "r"((a)[2]), "r"((a)[3]), "r"(b0), "r"(b1))

__global__ __launch_bounds__(256, 2) void gemm_tc_kernel(const float* __restrict__ bias,
                                                          int bn_base)
{
    extern __shared__ char smem[];
    const uint32_t sbase = (uint32_t)__cvta_generic_to_shared(smem);
    const int tid  = threadIdx.x;
    const int wid  = tid >> 5;
    const int lane = tid & 31;
    const int bm = blockIdx.y * BM;
    const int bn = bn_base + blockIdx.x * BN;

    const int warp_m = wid >> 2;
    const int warp_n = wid & 3;

    float acc[4][4][4];
    #pragma unroll
    for (int i = 0; i < 4; i++)
        #pragma unroll
        for (int j = 0; j < 4; j++)
            #pragma unroll
            for (int k = 0; k < 4; k++) acc[i][j][k] = 0.f;

    auto issue = [&](int stage, int c) {
        uint32_t st = sbase + stage * STAGE_SZ;
        #pragma unroll
        for (int t = 0; t < 8; t++) {
            int i = tid + t * 256;
            int sub = (i >> 10) & 1;
            int isB = (i >> 9) & 1;
            int idx = i & 511;
            int row = idx >> 2, seg = idx & 3;
            const uint32_t* gbase = isB ? g_wh : g_xh;
            int grow = (isB ? bn : bm) + row;
            const uint32_t* gsrc = gbase
                + (size_t)grow * (IN_F / 2) + c * 32 + sub * 16 + seg * 4;
            cp16(st + sub * SUB_SZ + isB * 10240 + row * PAD_STRIDE + seg * 16, gsrc);
        }
        asm volatile("cp.async.commit_group;" ::: "memory");
    };

    const int a_row  = warp_m * 64 + (lane & 15);
    const int a_half = lane >> 4;
    const int b_row  = warp_n * 32 + ((lane & 16) >> 1) + (lane & 7);
    const int b_half = (lane >> 3) & 1;

    issue(0, 0);

    const int NCHUNK = IN_F / 64;   // 16
    for (int c = 0; c < NCHUNK; c++) {
        asm volatile("cp.async.wait_group 0;" ::: "memory");
        __syncthreads();
        if (c + 1 < NCHUNK) issue((c + 1) & 1, c + 1);

        const uint32_t st = sbase + (c & 1) * STAGE_SZ;
        #pragma unroll
        for (int ks = 0; ks < 4; ks++) {
            const uint32_t sb2 = st + (ks >> 1) * SUB_SZ;
            const int kb = (ks & 1) * 32;
            uint32_t ah[4][4];
            #pragma unroll
            for (int im = 0; im < 4; im++) {
                uint32_t addr = sb2 + (a_row + im * 16) * PAD_STRIDE + kb + a_half * 16;
                LDM_X4(ah[im], addr);
            }
            uint32_t bh[8];
            #pragma unroll
            for (int g = 0; g < 2; g++) {
                uint32_t addr = sb2 + 10240 + (b_row + g * 16) * PAD_STRIDE + kb + b_half * 16;
                LDM_X4(bh + g * 4, addr);
            }
            #pragma unroll
            for (int im = 0; im < 4; im++) {
                #pragma unroll
                for (int in = 0; in < 4; in++) {
                    MMA16816(acc[im][in], ah[im], bh[in * 2], bh[in * 2 + 1]);
                }
            }
        }
    }

    // Epilogue: add bias, convert to half2, store packed fp16 hidden
    const int er = lane >> 2;
    const int ec = (lane & 3) * 2;
    #pragma unroll
    for (int im = 0; im < 4; im++) {
        int r0 = bm + warp_m * 64 + im * 16 + er;
        #pragma unroll
        for (int in = 0; in < 4; in++) {
            int col = bn + warp_n * 32 + in * 8 + ec;
            float b0 = __ldg(&bias[col]);
            float b1 = __ldg(&bias[col + 1]);
            uint32_t h0, h1;
            asm("cvt.rn.f16x2.f32 %0, %1, %2;" : "=r"(h0)
                : "f"(acc[im][in][1] + b1), "f"(acc[im][in][0] + b0));
            asm("cvt.rn.f16x2.f32 %0, %1, %2;" : "=r"(h1)
                : "f"(acc[im][in][3] + b1), "f"(acc[im][in][2] + b0));
            g_hidden[(size_t)r0 * (OUT_F / 2) + (col >> 1)] = h0;
            g_hidden[(size_t)(r0 + 8) * (OUT_F / 2) + (col >> 1)] = h1;
        }
    }
}

// ---------------------------------------------------------------------------
// Aggregate HALF (uint2 cols [base, base+64)):
// dedup via 1KB smem bitmask, then gather + relu.
// ---------------------------------------------------------------------------
__global__ __launch_bounds__(64) void aggregate_half_kernel(float* __restrict__ out,
                                                            int base)
{
    __shared__ uint32_t s_mask[N_NODES / 32];   // 1 KB
    __shared__ uint16_t s_list[NBR_STRIDE];
    __shared__ int s_n;

    const int row = blockIdx.x;
    const int t   = threadIdx.x;
    const int col = base + t;

    #pragma unroll
    for (int i = 0; i < (N_NODES / 32) / 64; i++)
        s_mask[t + i * 64] = 0u;
    if (t == 0) s_n = 0;
    __syncthreads();

    const int deg_raw = min(g_cnt[row], NBR_STRIDE);
    for (int i = t; i < deg_raw; i += 64) {
        int j = g_nbr[row * NBR_STRIDE + i];
        uint32_t bit = 1u << (j & 31);
        uint32_t old = atomicOr(&s_mask[j >> 5], bit);
        if (!(old & bit)) {
            int p = atomicAdd(&s_n, 1);
            s_list[p] = (uint16_t)j;
        }
    }
    __syncthreads();
    const int deg = s_n;

    const uint2* H = reinterpret_cast<const uint2*>(g_hidden);

    float4 a[8];
    #pragma unroll
    for (int k = 0; k < 8; k++) a[k] = make_float4(0.f, 0.f, 0.f, 0.f);

    auto acc4 = [](float4& a, uint2 u) {
        float2 lo = __half22float2(*reinterpret_cast<__half2*>(&u.x));
        float2 hi = __half22float2(*reinterpret_cast<__half2*>(&u.y));
        a.x += lo.x; a.y += lo.y; a.z += hi.x; a.w += hi.y;
    };

    int i = 0;
    for (; i + 8 <= deg; i += 8) {
        uint2 u[8];
        #pragma unroll
        for (int k = 0; k < 8; k++) u[k] = H[s_list[i + k] * 128 + col];
        #pragma unroll
        for (int k = 0; k < 8; k++) acc4(a[k], u[k]);
    }
    for (; i < deg; i++) {
        uint2 u = H[s_list[i] * 128 + col];
        acc4(a[0], u);
    }

    #pragma unroll
    for (int k = 4; k > 0; k >>= 1)
        #pragma unroll
        for (int j = 0; j < k; j++) {
            a[j].x += a[j + k].x; a[j].y += a[j + k].y;
            a[j].z += a[j + k].z; a[j].w += a[j + k].w;
        }

    float4 r;
    r.x = fmaxf(a[0].x, 0.f);
    r.y = fmaxf(a[0].y, 0.f);
    r.z = fmaxf(a[0].z, 0.f);
    r.w = fmaxf(a[0].w, 0.f);
    reinterpret_cast<float4*>(out)[row * 128 + col] = r;
}

// ---------------------------------------------------------------------------
// Launch topology:
//   s2: prep -> build -> [ev_build]            (fully off critical path)
//   s1: convert -> [ev_conv] -> gemmB -> (wait ev_build) agg1 -> [ev_d1]
//   s0: (wait ev_conv) gemmA -> (wait ev_build) agg0 -> (wait ev_d1)
// ---------------------------------------------------------------------------
extern "C" void kernel_launch(void* const* d_in, const int* in_sizes, int n_in,
                              void* d_out, int out_size)
{
    const float* x    = (const float*)d_in[0];
    const float* W    = (const float*)d_in[1];
    const float* bias = (const float*)d_in[2];
    const int*   ei   = (const int*)d_in[3];
    float*       out  = (float*)d_out;

    (void)in_sizes; (void)n_in; (void)out_size;

    static cudaStream_t s1, s2;
    static cudaEvent_t ev_fork, ev_conv, ev_build, ev_d1;
    static bool init = false;
    if (!init) {
        cudaStreamCreateWithFlags(&s1, cudaStreamNonBlocking);
        cudaStreamCreateWithFlags(&s2, cudaStreamNonBlocking);
        cudaEventCreateWithFlags(&ev_fork, cudaEventDisableTiming);
        cudaEventCreateWithFlags(&ev_conv, cudaEventDisableTiming);
        cudaEventCreateWithFlags(&ev_build, cudaEventDisableTiming);
        cudaEventCreateWithFlags(&ev_d1, cudaEventDisableTiming);
        cudaFuncSetAttribute(gemm_tc_kernel,
                             cudaFuncAttributeMaxDynamicSharedMemorySize, GEMM_SMEM);
        init = true;
    }

    dim3 ggrid(2, N_NODES / BM);            // half-N GEMM: (2, 64)

    // fork both side streams from s0
    cudaEventRecord(ev_fork, 0);
    cudaStreamWaitEvent(s1, ev_fork, 0);
    cudaStreamWaitEvent(s2, ev_fork, 0);

    // s2: graph prep (off critical path)
    prep_kernel<<<32, 256, 0, s2>>>(ei);
    build_kernel<<<N_EDGES / 2 / 256, 256, 0, s2>>>(ei);
    cudaEventRecord(ev_build, s2);

    // s1: convert -> gemmB -> agg1
    convert_kernel<<<1024, 256, 0, s1>>>(x, W);
    cudaEventRecord(ev_conv, s1);
    gemm_tc_kernel<<<ggrid, 256, GEMM_SMEM, s1>>>(bias, 256);
    cudaStreamWaitEvent(s1, ev_build, 0);
    aggregate_half_kernel<<<N_NODES, 64, 0, s1>>>(out, 64);
    cudaEventRecord(ev_d1, s1);

    // s0: gemmA -> agg0
    cudaStreamWaitEvent(0, ev_conv, 0);
    gemm_tc_kernel<<<ggrid, 256, GEMM_SMEM>>>(bias, 0);
    cudaStreamWaitEvent(0, ev_build, 0);
    aggregate_half_kernel<<<N_NODES, 64>>>(out, 0);

    // join
    cudaStreamWaitEvent(0, ev_d1, 0);
}